// round 9
// baseline (speedup 1.0000x reference)
#include <cuda_runtime.h>
#include <cuda_fp16.h>
#include <math.h>
#include <stdint.h>

#define BB     4
#define LSEQ   1024
#define INDIM  256
#define DM     512
#define NH     8
#define DHD    64
#define FFD    2048
#define NTOK   (BB*LSEQ)   // 4096

// ---------------- scratch (device globals: allocation-free) ----------------
__device__ float g_x   [NTOK*DM];
__device__ float g_xn  [NTOK*DM];
__device__ float g_qkv [NTOK*3*DM];
__device__ float g_ctx [NTOK*DM];
__device__ float g_h   [NTOK*FFD];
__device__ unsigned char g_rowall[NTOK];
__device__ __half g_bias[(size_t)NTOK*LSEQ];   // fused attention bias (fp16)
// tf32-pre-rounded GEMM inputs
__device__ float g_xr  [NTOK*INDIM];
__device__ float g_wf  [DM*INDIM];
__device__ float g_wqkv[3*DM*DM];
__device__ float g_wo  [DM*DM];
__device__ float g_w1  [FFD*DM];
__device__ float g_w2  [DM*FFD];

__device__ __forceinline__ uint32_t tf32r(float x) {
    uint32_t r; asm("cvt.rna.tf32.f32 %0, %1;" : "=r"(r) : "f"(x)); return r;
}
__device__ __forceinline__ float tf32f(float x) { return __uint_as_float(tf32r(x)); }
__device__ __forceinline__ void mma_tf32(float* c, const uint32_t* a, const uint32_t* b) {
    asm volatile(
        "mma.sync.aligned.m16n8k8.row.col.f32.tf32.tf32.f32 "
        "{%0,%1,%2,%3}, {%4,%5,%6,%7}, {%8,%9}, {%0,%1,%2,%3};"
        : "+f"(c[0]), "+f"(c[1]), "+f"(c[2]), "+f"(c[3])
        : "r"(a[0]), "r"(a[1]), "r"(a[2]), "r"(a[3]), "r"(b[0]), "r"(b[1]));
}
__device__ __forceinline__ uint32_t smem_u32(const void* p) {
    uint32_t a;
    asm("{ .reg .u64 t; cvta.to.shared.u64 t, %1; cvt.u32.u64 %0, t; }" : "=r"(a) : "l"(p));
    return a;
}
__device__ __forceinline__ void cpa16(uint32_t d, const void* s) {
    asm volatile("cp.async.ca.shared.global [%0], [%1], 16;" :: "r"(d), "l"(s));
}
__device__ __forceinline__ void cpa_commit() { asm volatile("cp.async.commit_group;" ::: "memory"); }
template<int N> __device__ __forceinline__ void cpa_wait() {
    asm volatile("cp.async.wait_group %0;" :: "n"(N) : "memory");
}

// ---------------- tf32 pre-round kernel ----------------
__global__ __launch_bounds__(256) void round_kernel(
    const float* __restrict__ src, float* __restrict__ dst, int n4)
{
    for (int i = blockIdx.x * 256 + threadIdx.x; i < n4; i += gridDim.x * 256) {
        float4 v = ((const float4*)src)[i];
        v.x = tf32f(v.x); v.y = tf32f(v.y); v.z = tf32f(v.z); v.w = tf32f(v.w);
        ((float4*)dst)[i] = v;
    }
}

// ================= tf32 mma.sync GEMM, cp.async 2-stage, BM templated =========
// C[M,N] = A[M,K] @ W[N,K]^T + bias[N]  (EPI: 0=bias, 1=+GELU(round), 2=+residual)
// Inputs pre-rounded tf32. BN=128, BK=32; 8 warps; BM=128: 4x2 warps (tile 32x64),
// BM=64: 2x4 warps (tile 32x32). smem [row][k] pad 44.
#define RP 44

template<int BM, int EPI>
__global__ __launch_bounds__(256, 2) void mma_gemm(
    const float* __restrict__ A, const float* __restrict__ W,
    const float* __restrict__ bias, const float* __restrict__ res,
    float* __restrict__ C, int M, int N, int K)
{
    constexpr int WMN = (BM == 128) ? 4 : 2;     // warps along m
    constexpr int NWN = 8 / WMN;                 // warps along n
    constexpr int NWIDTH = 128 / NWN;            // 64 or 32
    constexpr int NT = NWIDTH / 8;               // 8 or 4
    constexpr int ASTG = BM * RP;                // A uints / stage
    constexpr int STG  = ASTG + 128 * RP;        // stage uints
    constexpr int AROWS = BM / 32;

    extern __shared__ uint32_t sm[];
    const uint32_t sbase = smem_u32(sm);
    const int tid = threadIdx.x;
    const int bm = blockIdx.y * BM, bn = blockIdx.x * 128;
    const int lane = tid & 31, warp = tid >> 5;
    const int wm = warp % WMN, wn = warp / WMN;
    const int m_base = wm * 32, n_base = wn * NWIDTH;
    const int lg = lane >> 2, lt = lane & 3;

    float acc[2][NT][4];
    #pragma unroll
    for (int mt = 0; mt < 2; mt++)
        #pragma unroll
        for (int nt = 0; nt < NT; nt++)
            #pragma unroll
            for (int q = 0; q < 4; q++) acc[mt][nt][q] = 0.f;

    const int row = tid >> 3, kc = tid & 7;
    const float* Agp = A + (size_t)(bm + row) * K + kc * 4;
    const float* Bgp = W + (size_t)(bn + row) * K + kc * 4;
    const uint32_t sA_off = (row * RP + kc * 4) * 4;
    const uint32_t rowstride = 32 * RP * 4;
    const size_t gstride = (size_t)32 * K;

    const int nc = K / 32;
    {
        uint32_t sA = sbase + sA_off;
        uint32_t sB = sbase + ASTG * 4 + sA_off;
        #pragma unroll
        for (int i = 0; i < AROWS; i++) cpa16(sA + i * rowstride, Agp + i * gstride);
        #pragma unroll
        for (int i = 0; i < 4; i++)     cpa16(sB + i * rowstride, Bgp + i * gstride);
        cpa_commit();
    }

    for (int c = 0; c < nc; c++) {
        const int st = c & 1;
        if (c + 1 < nc) {
            uint32_t sA = sbase + ((c + 1) & 1) * (STG * 4) + sA_off;
            uint32_t sB = sA + ASTG * 4;
            const float* Ag = Agp + (c + 1) * 32;
            const float* Bg = Bgp + (c + 1) * 32;
            #pragma unroll
            for (int i = 0; i < AROWS; i++) cpa16(sA + i * rowstride, Ag + i * gstride);
            #pragma unroll
            for (int i = 0; i < 4; i++)     cpa16(sB + i * rowstride, Bg + i * gstride);
            cpa_commit();
            cpa_wait<1>();
        } else {
            cpa_wait<0>();
        }
        __syncthreads();

        const uint32_t* As = sm + st * STG;
        const uint32_t* Bs = As + ASTG;
        #pragma unroll
        for (int ks = 0; ks < 4; ks++) {
            const int k = ks * 8;
            uint32_t a[2][4], b[NT][2];
            #pragma unroll
            for (int mt = 0; mt < 2; mt++) {
                const int mr = m_base + mt * 16 + lg;
                a[mt][0] = As[mr * RP + k + lt];
                a[mt][1] = As[(mr + 8) * RP + k + lt];
                a[mt][2] = As[mr * RP + k + lt + 4];
                a[mt][3] = As[(mr + 8) * RP + k + lt + 4];
            }
            #pragma unroll
            for (int nt = 0; nt < NT; nt++) {
                const int nr = n_base + nt * 8 + lg;
                b[nt][0] = Bs[nr * RP + k + lt];
                b[nt][1] = Bs[nr * RP + k + lt + 4];
            }
            #pragma unroll
            for (int mt = 0; mt < 2; mt++)
                #pragma unroll
                for (int nt = 0; nt < NT; nt++)
                    mma_tf32(acc[mt][nt], a[mt], b[nt]);
        }
        __syncthreads();
    }

    #pragma unroll
    for (int mt = 0; mt < 2; mt++) {
        #pragma unroll
        for (int nt = 0; nt < NT; nt++) {
            const int rw = bm + m_base + mt * 16 + lg;
            const int col = bn + n_base + nt * 8 + lt * 2;
            #pragma unroll
            for (int half = 0; half < 2; half++) {
                const int r = rw + half * 8;
                float v0 = acc[mt][nt][half*2+0] + bias[col];
                float v1 = acc[mt][nt][half*2+1] + bias[col+1];
                if (EPI == 1) {
                    v0 = 0.5f * v0 * (1.f + erff(v0 * 0.70710678118654752f));
                    v1 = 0.5f * v1 * (1.f + erff(v1 * 0.70710678118654752f));
                    v0 = tf32f(v0); v1 = tf32f(v1);
                }
                if (EPI == 2) {
                    float2 rr = *(const float2*)(res + (size_t)r * N + col);
                    v0 += rr.x; v1 += rr.y;
                }
                *(float2*)(C + (size_t)r * N + col) = make_float2(v0, v1);
            }
        }
    }
}

// ---------------- layernorm (tf32-rounded output) ----------------
__global__ __launch_bounds__(128) void ln_kernel(
    const float* __restrict__ X, const float* __restrict__ g,
    const float* __restrict__ b, float* __restrict__ Y)
{
    const int row = blockIdx.x;
    const int tid = threadIdx.x;
    float4 v = *(const float4*)(X + (size_t)row*DM + tid*4);
    float s  = v.x + v.y + v.z + v.w;
    float s2 = v.x*v.x + v.y*v.y + v.z*v.z + v.w*v.w;
    #pragma unroll
    for (int off = 16; off >= 1; off >>= 1) {
        s  += __shfl_xor_sync(0xffffffffu, s,  off);
        s2 += __shfl_xor_sync(0xffffffffu, s2, off);
    }
    __shared__ float sh[8];
    if ((tid & 31) == 0) { sh[tid>>5] = s; sh[4 + (tid>>5)] = s2; }
    __syncthreads();
    s  = sh[0] + sh[1] + sh[2] + sh[3];
    s2 = sh[4] + sh[5] + sh[6] + sh[7];
    float mu  = s * (1.f/DM);
    float var = s2 * (1.f/DM) - mu*mu;
    float inv = rsqrtf(var + 1e-5f);
    float4 gg = *(const float4*)(g + tid*4);
    float4 bb = *(const float4*)(b + tid*4);
    float4 y;
    y.x = tf32f((v.x - mu)*inv*gg.x + bb.x);
    y.y = tf32f((v.y - mu)*inv*gg.y + bb.y);
    y.z = tf32f((v.z - mu)*inv*gg.z + bb.z);
    y.w = tf32f((v.w - mu)*inv*gg.w + bb.w);
    *(float4*)(Y + (size_t)row*DM + tid*4) = y;
}

// ---------------- row_all (mask int32 0/1) ----------------
__global__ __launch_bounds__(128) void rowall_kernel(
    const int* __restrict__ mask, unsigned char* __restrict__ out)
{
    const int row = blockIdx.x;
    const int tid = threadIdx.x;
    const int* m = mask + (size_t)row * LSEQ;
    int mn = 1;
    #pragma unroll
    for (int c = 0; c < LSEQ / 512; c++) {
        int4 v = *(const int4*)(m + c*512 + tid*4);
        mn = min(mn, min(min(v.x, v.y), min(v.z, v.w)));
    }
    #pragma unroll
    for (int off = 16; off >= 1; off >>= 1)
        mn = min(mn, __shfl_xor_sync(0xffffffffu, mn, off));
    __shared__ int sh[4];
    if ((tid & 31) == 0) sh[tid>>5] = mn;
    __syncthreads();
    if (tid == 0) {
        int r = min(min(sh[0], sh[1]), min(sh[2], sh[3]));
        out[row] = (r != 0) ? 1 : 0;
    }
}

// ---------------- fused bias prepass: fp16 bias = masking + scaled adj ------
// one block per (b,q) row; 256 threads x 4 cols.
__global__ __launch_bounds__(256) void bias_kernel(
    const int* __restrict__ mask, const float* __restrict__ adj,
    const unsigned char* __restrict__ rowall, const float* __restrict__ logscale,
    __half* __restrict__ bias)
{
    const int row = blockIdx.x;
    const int q = row & (LSEQ - 1);
    const float esc = expf(logscale[0]);
    const bool ra = rowall[row] != 0;
    const int i = threadIdx.x;
    const int4  mm = ((const int4*)(mask + (size_t)row * LSEQ))[i];
    const float4 ad = ((const float4*)(adj + (size_t)row * LSEQ))[i];
    const int c0 = i * 4;
    float v0 = ((mm.x != 0) && !((c0+0 == q) && ra) ? -10000.f : 0.f) + esc * __saturatef(ad.x);
    float v1 = ((mm.y != 0) && !((c0+1 == q) && ra) ? -10000.f : 0.f) + esc * __saturatef(ad.y);
    float v2 = ((mm.z != 0) && !((c0+2 == q) && ra) ? -10000.f : 0.f) + esc * __saturatef(ad.z);
    float v3 = ((mm.w != 0) && !((c0+3 == q) && ra) ? -10000.f : 0.f) + esc * __saturatef(ad.w);
    __half2* b2 = (__half2*)(bias + (size_t)row * LSEQ);
    b2[i*2+0] = __floats2half2_rn(v0, v1);
    b2[i*2+1] = __floats2half2_rn(v2, v3);
}

// ---------------- flash attention on tensor pipe (tf32 mma.sync) ----------------
#define APAD 68
#define VPAD 72
#define SM_Q 0
#define SM_K (64*APAD)
#define SM_P (2*64*APAD)
#define SM_V (3*64*APAD)
#define ATTN_SMEM ((3*64*APAD + 64*VPAD) * 4)

__global__ __launch_bounds__(128) void attn_mma(
    const float* __restrict__ qkv,
    const __half* __restrict__ bias,
    float* __restrict__ ctx)
{
    extern __shared__ uint32_t sm[];
    uint32_t* Qs = sm + SM_Q;
    uint32_t* Ks = sm + SM_K;
    uint32_t* Ps = sm + SM_P;
    uint32_t* Vs = sm + SM_V;

    const int b = blockIdx.z, h = blockIdx.y;
    const int q0 = blockIdx.x * 64;
    const int tid = threadIdx.x;
    const int lane = tid & 31, warp = tid >> 5;
    const int lg = lane >> 2, lt = lane & 3;
    const int mb = warp * 16;

    const int lrow = tid >> 1, lcb = (tid & 1) * 32;

    {
        const float* qg = qkv + (size_t)(b*LSEQ + q0 + lrow)*(3*DM) + h*DHD + lcb;
        #pragma unroll
        for (int i = 0; i < 8; i++) {
            float4 v = *(const float4*)(qg + i*4);
            uint32_t* dst = Qs + lrow*APAD + lcb + i*4;
            dst[0] = tf32r(v.x); dst[1] = tf32r(v.y);
            dst[2] = tf32r(v.z); dst[3] = tf32r(v.w);
        }
    }
    __syncthreads();

    uint32_t qa[8][4];
    #pragma unroll
    for (int ks = 0; ks < 8; ks++) {
        const int k8 = ks * 8;
        qa[ks][0] = Qs[(mb+lg  )*APAD + k8 + lt];
        qa[ks][1] = Qs[(mb+lg+8)*APAD + k8 + lt];
        qa[ks][2] = Qs[(mb+lg  )*APAD + k8 + lt + 4];
        qa[ks][3] = Qs[(mb+lg+8)*APAD + k8 + lt + 4];
    }

    float o[8][4];
    #pragma unroll
    for (int nt = 0; nt < 8; nt++)
        #pragma unroll
        for (int q = 0; q < 4; q++) o[nt][q] = 0.f;
    float mi[2] = {-1e30f, -1e30f}, li[2] = {0.f, 0.f};

    const int qrow[2] = { q0 + mb + lg, q0 + mb + lg + 8 };

    for (int k0 = 0; k0 < LSEQ; k0 += 64) {
        {
            const float* kg = qkv + (size_t)(b*LSEQ + k0 + lrow)*(3*DM) + DM + h*DHD + lcb;
            const float* vg = kg + DM;
            #pragma unroll
            for (int i = 0; i < 8; i++) {
                float4 kv = *(const float4*)(kg + i*4);
                uint32_t* kd = Ks + lrow*APAD + lcb + i*4;
                kd[0] = tf32r(kv.x); kd[1] = tf32r(kv.y);
                kd[2] = tf32r(kv.z); kd[3] = tf32r(kv.w);
                float4 vv = *(const float4*)(vg + i*4);
                uint32_t* vd = Vs + lrow*VPAD + lcb + i*4;
                vd[0] = tf32r(vv.x); vd[1] = tf32r(vv.y);
                vd[2] = tf32r(vv.z); vd[3] = tf32r(vv.w);
            }
        }
        __syncthreads();

        float s[8][4];
        #pragma unroll
        for (int nt = 0; nt < 8; nt++)
            #pragma unroll
            for (int q = 0; q < 4; q++) s[nt][q] = 0.f;
        #pragma unroll
        for (int ks = 0; ks < 8; ks++) {
            const int k8 = ks * 8;
            #pragma unroll
            for (int nt = 0; nt < 8; nt++) {
                uint32_t bfr[2];
                bfr[0] = Ks[(nt*8+lg)*APAD + k8 + lt];
                bfr[1] = Ks[(nt*8+lg)*APAD + k8 + lt + 4];
                mma_tf32(s[nt], qa[ks], bfr);
            }
        }

        #pragma unroll
        for (int r = 0; r < 2; r++) {
            const __half2* brow = (const __half2*)(bias + ((size_t)b*LSEQ + qrow[r])*LSEQ + k0);
            float rmax = -1e30f;
            #pragma unroll
            for (int nt = 0; nt < 8; nt++) {
                const float2 bv = __half22float2(brow[nt*4 + lt]);
                float v0 = s[nt][2*r  ]*0.125f + bv.x;
                float v1 = s[nt][2*r+1]*0.125f + bv.y;
                s[nt][2*r  ] = v0; s[nt][2*r+1] = v1;
                rmax = fmaxf(rmax, fmaxf(v0, v1));
            }
            rmax = fmaxf(rmax, __shfl_xor_sync(0xffffffffu, rmax, 1));
            rmax = fmaxf(rmax, __shfl_xor_sync(0xffffffffu, rmax, 2));
            float mnew = fmaxf(mi[r], rmax);
            float corr = __expf(mi[r] - mnew);
            float psum = 0.f;
            #pragma unroll
            for (int nt = 0; nt < 8; nt++) {
                float p0 = __expf(s[nt][2*r  ] - mnew);
                float p1 = __expf(s[nt][2*r+1] - mnew);
                s[nt][2*r] = p0; s[nt][2*r+1] = p1;
                psum += p0 + p1;
            }
            psum += __shfl_xor_sync(0xffffffffu, psum, 1);
            psum += __shfl_xor_sync(0xffffffffu, psum, 2);
            li[r] = li[r]*corr + psum;
            mi[r] = mnew;
            #pragma unroll
            for (int nt = 0; nt < 8; nt++) { o[nt][2*r] *= corr; o[nt][2*r+1] *= corr; }
            #pragma unroll
            for (int nt = 0; nt < 8; nt++) {
                uint32_t* pd = Ps + (mb+lg+8*r)*APAD + nt*8 + lt*2;
                pd[0] = tf32r(s[nt][2*r]); pd[1] = tf32r(s[nt][2*r+1]);
            }
        }
        __syncthreads();

        #pragma unroll
        for (int ks = 0; ks < 8; ks++) {
            const int k8 = ks * 8;
            uint32_t pa[4];
            pa[0] = Ps[(mb+lg  )*APAD + k8 + lt];
            pa[1] = Ps[(mb+lg+8)*APAD + k8 + lt];
            pa[2] = Ps[(mb+lg  )*APAD + k8 + lt + 4];
            pa[3] = Ps[(mb+lg+8)*APAD + k8 + lt + 4];
            #pragma unroll
            for (int nt = 0; nt < 8; nt++) {
                uint32_t bfr[2];
                bfr[0] = Vs[(k8+lt  )*VPAD + nt*8 + lg];
                bfr[1] = Vs[(k8+lt+4)*VPAD + nt*8 + lg];
                mma_tf32(o[nt], pa, bfr);
            }
        }
        __syncthreads();
    }

    const float inv0 = 1.f / li[0], inv1 = 1.f / li[1];
    #pragma unroll
    for (int nt = 0; nt < 8; nt++) {
        const int col = h*DHD + nt*8 + lt*2;
        *(float2*)(ctx + (size_t)(b*LSEQ + qrow[0])*DM + col) =
            make_float2(tf32f(o[nt][0]*inv0), tf32f(o[nt][1]*inv0));
        *(float2*)(ctx + (size_t)(b*LSEQ + qrow[1])*DM + col) =
            make_float2(tf32f(o[nt][2]*inv1), tf32f(o[nt][3]*inv1));
    }
}

// ---------------- launch ----------------
extern "C" void kernel_launch(void* const* d_in, const int* in_sizes, int n_in,
                              void* d_out, int out_size)
{
    (void)in_sizes; (void)n_in; (void)out_size;
    const float* x      = (const float*)d_in[0];
    const int*   amask  = (const int*)d_in[1];
    const float* adj    = (const float*)d_in[2];
    const float* Wf     = (const float*)d_in[3];
    const float* bf     = (const float*)d_in[4];
    const float* Wqkv   = (const float*)d_in[5];
    const float* bqkv   = (const float*)d_in[6];
    const float* Wo     = (const float*)d_in[7];
    const float* bo     = (const float*)d_in[8];
    const float* ln1g   = (const float*)d_in[9];
    const float* ln1b   = (const float*)d_in[10];
    const float* ln2g   = (const float*)d_in[11];
    const float* ln2b   = (const float*)d_in[12];
    const float* W1     = (const float*)d_in[13];
    const float* b1     = (const float*)d_in[14];
    const float* W2     = (const float*)d_in[15];
    const float* b2     = (const float*)d_in[16];
    const float* lscale = (const float*)d_in[17];
    float* out = (float*)d_out;

    float *gx, *gxn, *gqkv, *gctx, *gh;
    float *gxr, *gwf, *gwqkv, *gwo, *gw1, *gw2;
    unsigned char* grow; __half* gbias;
    cudaGetSymbolAddress((void**)&gx,    g_x);
    cudaGetSymbolAddress((void**)&gxn,   g_xn);
    cudaGetSymbolAddress((void**)&gqkv,  g_qkv);
    cudaGetSymbolAddress((void**)&gctx,  g_ctx);
    cudaGetSymbolAddress((void**)&gh,    g_h);
    cudaGetSymbolAddress((void**)&grow,  g_rowall);
    cudaGetSymbolAddress((void**)&gbias, g_bias);
    cudaGetSymbolAddress((void**)&gxr,   g_xr);
    cudaGetSymbolAddress((void**)&gwf,   g_wf);
    cudaGetSymbolAddress((void**)&gwqkv, g_wqkv);
    cudaGetSymbolAddress((void**)&gwo,   g_wo);
    cudaGetSymbolAddress((void**)&gw1,   g_w1);
    cudaGetSymbolAddress((void**)&gw2,   g_w2);

    const int SMB128 = 2 * (128 + 128) * RP * 4;   // 90112
    const int SMB64  = 2 * (64  + 128) * RP * 4;   // 67584
    cudaFuncSetAttribute((const void*)mma_gemm<128,0>, cudaFuncAttributeMaxDynamicSharedMemorySize, SMB128);
    cudaFuncSetAttribute((const void*)mma_gemm<128,1>, cudaFuncAttributeMaxDynamicSharedMemorySize, SMB128);
    cudaFuncSetAttribute((const void*)mma_gemm<64,0>,  cudaFuncAttributeMaxDynamicSharedMemorySize, SMB64);
    cudaFuncSetAttribute((const void*)mma_gemm<64,2>,  cudaFuncAttributeMaxDynamicSharedMemorySize, SMB64);
    cudaFuncSetAttribute((const void*)attn_mma,        cudaFuncAttributeMaxDynamicSharedMemorySize, ATTN_SMEM);

    // 0. pre-round GEMM inputs to tf32
    round_kernel<<<512, 256>>>(x,    gxr,   NTOK*INDIM/4);
    round_kernel<<<128, 256>>>(Wf,   gwf,   DM*INDIM/4);
    round_kernel<<<512, 256>>>(Wqkv, gwqkv, 3*DM*DM/4);
    round_kernel<<<256, 256>>>(Wo,   gwo,   DM*DM/4);
    round_kernel<<<512, 256>>>(W1,   gw1,   FFD*DM/4);
    round_kernel<<<512, 256>>>(W2,   gw2,   DM*FFD/4);

    // 1. row_all + fused fp16 bias prepass
    rowall_kernel<<<NTOK, 128>>>(amask, grow);
    bias_kernel<<<NTOK, 256>>>(amask, adj, grow, lscale, gbias);

    // 2. fuse projection: g_x = x @ Wf^T + bf   (BM=64: 256 CTAs)
    mma_gemm<64,0><<<dim3(DM/128, NTOK/64), 256, SMB64>>>(gxr, gwf, bf, nullptr, gx, NTOK, DM, INDIM);
    // 3. LN1
    ln_kernel<<<NTOK, 128>>>(gx, ln1g, ln1b, gxn);
    // 4. qkv (BM=128: 384 CTAs)
    mma_gemm<128,0><<<dim3((3*DM)/128, NTOK/128), 256, SMB128>>>(gxn, gwqkv, bqkv, nullptr, gqkv, NTOK, 3*DM, DM);
    // 5. attention (tensor pipe, fp16 fused bias)
    attn_mma<<<dim3(LSEQ/64, NH, BB), 128, ATTN_SMEM>>>(gqkv, gbias, gctx);
    // 6. out proj + residual (BM=64)
    mma_gemm<64,2><<<dim3(DM/128, NTOK/64), 256, SMB64>>>(gctx, gwo, bo, gx, gx, NTOK, DM, DM);
    // 7. LN2
    ln_kernel<<<NTOK, 128>>>(gx, ln2g, ln2b, gxn);
    // 8. FFN up + GELU (BM=128: 512 CTAs)
    mma_gemm<128,1><<<dim3(FFD/128, NTOK/128), 256, SMB128>>>(gxn, gw1, b1, nullptr, gh, NTOK, FFD, DM);
    // 9. FFN down + residual -> out (BM=64: 256 CTAs)
    mma_gemm<64,2><<<dim3(DM/128, NTOK/64), 256, SMB64>>>(gh, gw2, b2, gx, out, NTOK, DM, FFD);
}

// round 10
// speedup vs baseline: 1.0274x; 1.0274x over previous
#include <cuda_runtime.h>
#include <cuda_fp16.h>
#include <math.h>
#include <stdint.h>

#define BB     4
#define LSEQ   1024
#define INDIM  256
#define DM     512
#define NH     8
#define DHD    64
#define FFD    2048
#define NTOK   (BB*LSEQ)   // 4096

// ---------------- scratch (device globals: allocation-free) ----------------
__device__ float g_x   [NTOK*DM];
__device__ float g_xn  [NTOK*DM];
__device__ float g_qkv [NTOK*3*DM];
__device__ float g_ctx [NTOK*DM];
__device__ float g_h   [NTOK*FFD];
__device__ unsigned char g_rowall[NTOK];
__device__ __half g_bias[(size_t)NTOK*LSEQ];   // fused attention bias (fp16)
// tf32-pre-rounded GEMM inputs
__device__ float g_xr  [NTOK*INDIM];
__device__ float g_wf  [DM*INDIM];
__device__ float g_wqkv[3*DM*DM];
__device__ float g_wo  [DM*DM];
__device__ float g_w1  [FFD*DM];
__device__ float g_w2  [DM*FFD];

__device__ __forceinline__ uint32_t tf32r(float x) {
    uint32_t r; asm("cvt.rna.tf32.f32 %0, %1;" : "=r"(r) : "f"(x)); return r;
}
__device__ __forceinline__ float tf32f(float x) { return __uint_as_float(tf32r(x)); }
__device__ __forceinline__ void mma_tf32(float* c, const uint32_t* a, const uint32_t* b) {
    asm volatile(
        "mma.sync.aligned.m16n8k8.row.col.f32.tf32.tf32.f32 "
        "{%0,%1,%2,%3}, {%4,%5,%6,%7}, {%8,%9}, {%0,%1,%2,%3};"
        : "+f"(c[0]), "+f"(c[1]), "+f"(c[2]), "+f"(c[3])
        : "r"(a[0]), "r"(a[1]), "r"(a[2]), "r"(a[3]), "r"(b[0]), "r"(b[1]));
}
__device__ __forceinline__ uint32_t smem_u32(const void* p) {
    uint32_t a;
    asm("{ .reg .u64 t; cvta.to.shared.u64 t, %1; cvt.u32.u64 %0, t; }" : "=r"(a) : "l"(p));
    return a;
}
__device__ __forceinline__ void cpa16(uint32_t d, const void* s) {
    asm volatile("cp.async.ca.shared.global [%0], [%1], 16;" :: "r"(d), "l"(s));
}
__device__ __forceinline__ void cpa_commit() { asm volatile("cp.async.commit_group;" ::: "memory"); }
template<int N> __device__ __forceinline__ void cpa_wait() {
    asm volatile("cp.async.wait_group %0;" :: "n"(N) : "memory");
}

// ---------------- tf32 pre-round kernel ----------------
__global__ __launch_bounds__(256) void round_kernel(
    const float* __restrict__ src, float* __restrict__ dst, int n4)
{
    for (int i = blockIdx.x * 256 + threadIdx.x; i < n4; i += gridDim.x * 256) {
        float4 v = ((const float4*)src)[i];
        v.x = tf32f(v.x); v.y = tf32f(v.y); v.z = tf32f(v.z); v.w = tf32f(v.w);
        ((float4*)dst)[i] = v;
    }
}

// ================= tf32 mma.sync GEMM, cp.async 2-stage (R8 proven config) ====
// C[M,N] = A[M,K] @ W[N,K]^T + bias[N]  (EPI: 0=bias, 1=+GELU(round), 2=+residual)
// Inputs pre-rounded tf32. BM=BN=128, BK=32; 8 warps 4(m)x2(n), warp tile 32x64.
// smem [row][k] pad 44.
#define RP   44
#define STGU (2 * 128 * RP)            // uints per stage (A then B)
#define GSMB (2 * STGU * 4)            // total dyn smem bytes (90112)

template<int EPI>
__global__ __launch_bounds__(256, 2) void mma_gemm(
    const float* __restrict__ A, const float* __restrict__ W,
    const float* __restrict__ bias, const float* __restrict__ res,
    float* __restrict__ C, int M, int N, int K)
{
    extern __shared__ uint32_t sm[];
    const uint32_t sbase = smem_u32(sm);
    const int tid = threadIdx.x;
    const int bm = blockIdx.y * 128, bn = blockIdx.x * 128;
    const int lane = tid & 31, warp = tid >> 5;
    const int wm = warp & 3, wn = warp >> 2;
    const int m_base = wm * 32, n_base = wn * 64;
    const int lg = lane >> 2, lt = lane & 3;

    float acc[2][8][4];
    #pragma unroll
    for (int mt = 0; mt < 2; mt++)
        #pragma unroll
        for (int nt = 0; nt < 8; nt++)
            #pragma unroll
            for (int q = 0; q < 4; q++) acc[mt][nt][q] = 0.f;

    const int row = tid >> 3, kc = tid & 7;
    const float* Agp = A + (size_t)(bm + row) * K + kc * 4;
    const float* Bgp = W + (size_t)(bn + row) * K + kc * 4;
    const uint32_t sA_off = (row * RP + kc * 4) * 4;
    const uint32_t rowstride = 32 * RP * 4;
    const size_t gstride = (size_t)32 * K;

    const int nc = K / 32;
    {
        uint32_t sA = sbase + sA_off;
        uint32_t sB = sA + 128 * RP * 4;
        #pragma unroll
        for (int i = 0; i < 4; i++) {
            cpa16(sA + i * rowstride, Agp + i * gstride);
            cpa16(sB + i * rowstride, Bgp + i * gstride);
        }
        cpa_commit();
    }

    for (int c = 0; c < nc; c++) {
        const int st = c & 1;
        if (c + 1 < nc) {
            uint32_t sA = sbase + ((c + 1) & 1) * (STGU * 4) + sA_off;
            uint32_t sB = sA + 128 * RP * 4;
            const float* Ag = Agp + (c + 1) * 32;
            const float* Bg = Bgp + (c + 1) * 32;
            #pragma unroll
            for (int i = 0; i < 4; i++) {
                cpa16(sA + i * rowstride, Ag + i * gstride);
                cpa16(sB + i * rowstride, Bg + i * gstride);
            }
            cpa_commit();
            cpa_wait<1>();
        } else {
            cpa_wait<0>();
        }
        __syncthreads();

        const uint32_t* As = sm + st * STGU;
        const uint32_t* Bs = As + 128 * RP;
        #pragma unroll
        for (int ks = 0; ks < 4; ks++) {
            const int k = ks * 8;
            uint32_t a[2][4], b[8][2];
            #pragma unroll
            for (int mt = 0; mt < 2; mt++) {
                const int mr = m_base + mt * 16 + lg;
                a[mt][0] = As[mr * RP + k + lt];
                a[mt][1] = As[(mr + 8) * RP + k + lt];
                a[mt][2] = As[mr * RP + k + lt + 4];
                a[mt][3] = As[(mr + 8) * RP + k + lt + 4];
            }
            #pragma unroll
            for (int nt = 0; nt < 8; nt++) {
                const int nr = n_base + nt * 8 + lg;
                b[nt][0] = Bs[nr * RP + k + lt];
                b[nt][1] = Bs[nr * RP + k + lt + 4];
            }
            #pragma unroll
            for (int mt = 0; mt < 2; mt++)
                #pragma unroll
                for (int nt = 0; nt < 8; nt++)
                    mma_tf32(acc[mt][nt], a[mt], b[nt]);
        }
        __syncthreads();
    }

    #pragma unroll
    for (int mt = 0; mt < 2; mt++) {
        #pragma unroll
        for (int nt = 0; nt < 8; nt++) {
            const int rw = bm + m_base + mt * 16 + lg;
            const int col = bn + n_base + nt * 8 + lt * 2;
            #pragma unroll
            for (int half = 0; half < 2; half++) {
                const int r = rw + half * 8;
                float v0 = acc[mt][nt][half*2+0] + bias[col];
                float v1 = acc[mt][nt][half*2+1] + bias[col+1];
                if (EPI == 1) {
                    v0 = 0.5f * v0 * (1.f + erff(v0 * 0.70710678118654752f));
                    v1 = 0.5f * v1 * (1.f + erff(v1 * 0.70710678118654752f));
                    v0 = tf32f(v0); v1 = tf32f(v1);
                }
                if (EPI == 2) {
                    float2 rr = *(const float2*)(res + (size_t)r * N + col);
                    v0 += rr.x; v1 += rr.y;
                }
                *(float2*)(C + (size_t)r * N + col) = make_float2(v0, v1);
            }
        }
    }
}

// ---------------- layernorm (tf32-rounded output) ----------------
__global__ __launch_bounds__(128) void ln_kernel(
    const float* __restrict__ X, const float* __restrict__ g,
    const float* __restrict__ b, float* __restrict__ Y)
{
    const int row = blockIdx.x;
    const int tid = threadIdx.x;
    float4 v = *(const float4*)(X + (size_t)row*DM + tid*4);
    float s  = v.x + v.y + v.z + v.w;
    float s2 = v.x*v.x + v.y*v.y + v.z*v.z + v.w*v.w;
    #pragma unroll
    for (int off = 16; off >= 1; off >>= 1) {
        s  += __shfl_xor_sync(0xffffffffu, s,  off);
        s2 += __shfl_xor_sync(0xffffffffu, s2, off);
    }
    __shared__ float sh[8];
    if ((tid & 31) == 0) { sh[tid>>5] = s; sh[4 + (tid>>5)] = s2; }
    __syncthreads();
    s  = sh[0] + sh[1] + sh[2] + sh[3];
    s2 = sh[4] + sh[5] + sh[6] + sh[7];
    float mu  = s * (1.f/DM);
    float var = s2 * (1.f/DM) - mu*mu;
    float inv = rsqrtf(var + 1e-5f);
    float4 gg = *(const float4*)(g + tid*4);
    float4 bb = *(const float4*)(b + tid*4);
    float4 y;
    y.x = tf32f((v.x - mu)*inv*gg.x + bb.x);
    y.y = tf32f((v.y - mu)*inv*gg.y + bb.y);
    y.z = tf32f((v.z - mu)*inv*gg.z + bb.z);
    y.w = tf32f((v.w - mu)*inv*gg.w + bb.w);
    *(float4*)(Y + (size_t)row*DM + tid*4) = y;
}

// ---------------- row_all (mask int32 0/1) ----------------
__global__ __launch_bounds__(128) void rowall_kernel(
    const int* __restrict__ mask, unsigned char* __restrict__ out)
{
    const int row = blockIdx.x;
    const int tid = threadIdx.x;
    const int* m = mask + (size_t)row * LSEQ;
    int mn = 1;
    #pragma unroll
    for (int c = 0; c < LSEQ / 512; c++) {
        int4 v = *(const int4*)(m + c*512 + tid*4);
        mn = min(mn, min(min(v.x, v.y), min(v.z, v.w)));
    }
    #pragma unroll
    for (int off = 16; off >= 1; off >>= 1)
        mn = min(mn, __shfl_xor_sync(0xffffffffu, mn, off));
    __shared__ int sh[4];
    if ((tid & 31) == 0) sh[tid>>5] = mn;
    __syncthreads();
    if (tid == 0) {
        int r = min(min(sh[0], sh[1]), min(sh[2], sh[3]));
        out[row] = (r != 0) ? 1 : 0;
    }
}

// ---------------- fused bias prepass: fp16 bias = masking + scaled adj ------
__global__ __launch_bounds__(256) void bias_kernel(
    const int* __restrict__ mask, const float* __restrict__ adj,
    const unsigned char* __restrict__ rowall, const float* __restrict__ logscale,
    __half* __restrict__ bias)
{
    const int row = blockIdx.x;
    const int q = row & (LSEQ - 1);
    const float esc = expf(logscale[0]);
    const bool ra = rowall[row] != 0;
    const int i = threadIdx.x;
    const int4  mm = ((const int4*)(mask + (size_t)row * LSEQ))[i];
    const float4 ad = ((const float4*)(adj + (size_t)row * LSEQ))[i];
    const int c0 = i * 4;
    float v0 = ((mm.x != 0) && !((c0+0 == q) && ra) ? -10000.f : 0.f) + esc * __saturatef(ad.x);
    float v1 = ((mm.y != 0) && !((c0+1 == q) && ra) ? -10000.f : 0.f) + esc * __saturatef(ad.y);
    float v2 = ((mm.z != 0) && !((c0+2 == q) && ra) ? -10000.f : 0.f) + esc * __saturatef(ad.z);
    float v3 = ((mm.w != 0) && !((c0+3 == q) && ra) ? -10000.f : 0.f) + esc * __saturatef(ad.w);
    __half2* b2 = (__half2*)(bias + (size_t)row * LSEQ);
    b2[i*2+0] = __floats2half2_rn(v0, v1);
    b2[i*2+1] = __floats2half2_rn(v2, v3);
}

// ---------------- flash attention on tensor pipe (tf32 mma.sync) ----------------
#define APAD 68
#define VPAD 72
#define SM_Q 0
#define SM_K (64*APAD)
#define SM_P (2*64*APAD)
#define SM_V (3*64*APAD)
#define ATTN_SMEM ((3*64*APAD + 64*VPAD) * 4)

__global__ __launch_bounds__(128) void attn_mma(
    const float* __restrict__ qkv,
    const __half* __restrict__ bias,
    float* __restrict__ ctx)
{
    extern __shared__ uint32_t sm[];
    uint32_t* Qs = sm + SM_Q;
    uint32_t* Ks = sm + SM_K;
    uint32_t* Ps = sm + SM_P;
    uint32_t* Vs = sm + SM_V;

    const int b = blockIdx.z, h = blockIdx.y;
    const int q0 = blockIdx.x * 64;
    const int tid = threadIdx.x;
    const int lane = tid & 31, warp = tid >> 5;
    const int lg = lane >> 2, lt = lane & 3;
    const int mb = warp * 16;

    const int lrow = tid >> 1, lcb = (tid & 1) * 32;

    {
        const float* qg = qkv + (size_t)(b*LSEQ + q0 + lrow)*(3*DM) + h*DHD + lcb;
        #pragma unroll
        for (int i = 0; i < 8; i++) {
            float4 v = *(const float4*)(qg + i*4);
            uint32_t* dst = Qs + lrow*APAD + lcb + i*4;
            dst[0] = tf32r(v.x); dst[1] = tf32r(v.y);
            dst[2] = tf32r(v.z); dst[3] = tf32r(v.w);
        }
    }
    __syncthreads();

    uint32_t qa[8][4];
    #pragma unroll
    for (int ks = 0; ks < 8; ks++) {
        const int k8 = ks * 8;
        qa[ks][0] = Qs[(mb+lg  )*APAD + k8 + lt];
        qa[ks][1] = Qs[(mb+lg+8)*APAD + k8 + lt];
        qa[ks][2] = Qs[(mb+lg  )*APAD + k8 + lt + 4];
        qa[ks][3] = Qs[(mb+lg+8)*APAD + k8 + lt + 4];
    }

    float o[8][4];
    #pragma unroll
    for (int nt = 0; nt < 8; nt++)
        #pragma unroll
        for (int q = 0; q < 4; q++) o[nt][q] = 0.f;
    float mi[2] = {-1e30f, -1e30f}, li[2] = {0.f, 0.f};

    const int qrow[2] = { q0 + mb + lg, q0 + mb + lg + 8 };

    for (int k0 = 0; k0 < LSEQ; k0 += 64) {
        {
            const float* kg = qkv + (size_t)(b*LSEQ + k0 + lrow)*(3*DM) + DM + h*DHD + lcb;
            const float* vg = kg + DM;
            #pragma unroll
            for (int i = 0; i < 8; i++) {
                float4 kv = *(const float4*)(kg + i*4);
                uint32_t* kd = Ks + lrow*APAD + lcb + i*4;
                kd[0] = tf32r(kv.x); kd[1] = tf32r(kv.y);
                kd[2] = tf32r(kv.z); kd[3] = tf32r(kv.w);
                float4 vv = *(const float4*)(vg + i*4);
                uint32_t* vd = Vs + lrow*VPAD + lcb + i*4;
                vd[0] = tf32r(vv.x); vd[1] = tf32r(vv.y);
                vd[2] = tf32r(vv.z); vd[3] = tf32r(vv.w);
            }
        }
        __syncthreads();

        float s[8][4];
        #pragma unroll
        for (int nt = 0; nt < 8; nt++)
            #pragma unroll
            for (int q = 0; q < 4; q++) s[nt][q] = 0.f;
        #pragma unroll
        for (int ks = 0; ks < 8; ks++) {
            const int k8 = ks * 8;
            #pragma unroll
            for (int nt = 0; nt < 8; nt++) {
                uint32_t bfr[2];
                bfr[0] = Ks[(nt*8+lg)*APAD + k8 + lt];
                bfr[1] = Ks[(nt*8+lg)*APAD + k8 + lt + 4];
                mma_tf32(s[nt], qa[ks], bfr);
            }
        }

        #pragma unroll
        for (int r = 0; r < 2; r++) {
            const __half2* brow = (const __half2*)(bias + ((size_t)b*LSEQ + qrow[r])*LSEQ + k0);
            float rmax = -1e30f;
            #pragma unroll
            for (int nt = 0; nt < 8; nt++) {
                const float2 bv = __half22float2(brow[nt*4 + lt]);
                float v0 = s[nt][2*r  ]*0.125f + bv.x;
                float v1 = s[nt][2*r+1]*0.125f + bv.y;
                s[nt][2*r  ] = v0; s[nt][2*r+1] = v1;
                rmax = fmaxf(rmax, fmaxf(v0, v1));
            }
            rmax = fmaxf(rmax, __shfl_xor_sync(0xffffffffu, rmax, 1));
            rmax = fmaxf(rmax, __shfl_xor_sync(0xffffffffu, rmax, 2));
            float mnew = fmaxf(mi[r], rmax);
            float corr = __expf(mi[r] - mnew);
            float psum = 0.f;
            #pragma unroll
            for (int nt = 0; nt < 8; nt++) {
                float p0 = __expf(s[nt][2*r  ] - mnew);
                float p1 = __expf(s[nt][2*r+1] - mnew);
                s[nt][2*r] = p0; s[nt][2*r+1] = p1;
                psum += p0 + p1;
            }
            psum += __shfl_xor_sync(0xffffffffu, psum, 1);
            psum += __shfl_xor_sync(0xffffffffu, psum, 2);
            li[r] = li[r]*corr + psum;
            mi[r] = mnew;
            #pragma unroll
            for (int nt = 0; nt < 8; nt++) { o[nt][2*r] *= corr; o[nt][2*r+1] *= corr; }
            #pragma unroll
            for (int nt = 0; nt < 8; nt++) {
                uint32_t* pd = Ps + (mb+lg+8*r)*APAD + nt*8 + lt*2;
                pd[0] = tf32r(s[nt][2*r]); pd[1] = tf32r(s[nt][2*r+1]);
            }
        }
        __syncthreads();

        #pragma unroll
        for (int ks = 0; ks < 8; ks++) {
            const int k8 = ks * 8;
            uint32_t pa[4];
            pa[0] = Ps[(mb+lg  )*APAD + k8 + lt];
            pa[1] = Ps[(mb+lg+8)*APAD + k8 + lt];
            pa[2] = Ps[(mb+lg  )*APAD + k8 + lt + 4];
            pa[3] = Ps[(mb+lg+8)*APAD + k8 + lt + 4];
            #pragma unroll
            for (int nt = 0; nt < 8; nt++) {
                uint32_t bfr[2];
                bfr[0] = Vs[(k8+lt  )*VPAD + nt*8 + lg];
                bfr[1] = Vs[(k8+lt+4)*VPAD + nt*8 + lg];
                mma_tf32(o[nt], pa, bfr);
            }
        }
        __syncthreads();
    }

    const float inv0 = 1.f / li[0], inv1 = 1.f / li[1];
    #pragma unroll
    for (int nt = 0; nt < 8; nt++) {
        const int col = h*DHD + nt*8 + lt*2;
        *(float2*)(ctx + (size_t)(b*LSEQ + qrow[0])*DM + col) =
            make_float2(tf32f(o[nt][0]*inv0), tf32f(o[nt][1]*inv0));
        *(float2*)(ctx + (size_t)(b*LSEQ + qrow[1])*DM + col) =
            make_float2(tf32f(o[nt][2]*inv1), tf32f(o[nt][3]*inv1));
    }
}

// ---------------- launch ----------------
extern "C" void kernel_launch(void* const* d_in, const int* in_sizes, int n_in,
                              void* d_out, int out_size)
{
    (void)in_sizes; (void)n_in; (void)out_size;
    const float* x      = (const float*)d_in[0];
    const int*   amask  = (const int*)d_in[1];
    const float* adj    = (const float*)d_in[2];
    const float* Wf     = (const float*)d_in[3];
    const float* bf     = (const float*)d_in[4];
    const float* Wqkv   = (const float*)d_in[5];
    const float* bqkv   = (const float*)d_in[6];
    const float* Wo     = (const float*)d_in[7];
    const float* bo     = (const float*)d_in[8];
    const float* ln1g   = (const float*)d_in[9];
    const float* ln1b   = (const float*)d_in[10];
    const float* ln2g   = (const float*)d_in[11];
    const float* ln2b   = (const float*)d_in[12];
    const float* W1     = (const float*)d_in[13];
    const float* b1     = (const float*)d_in[14];
    const float* W2     = (const float*)d_in[15];
    const float* b2     = (const float*)d_in[16];
    const float* lscale = (const float*)d_in[17];
    float* out = (float*)d_out;

    float *gx, *gxn, *gqkv, *gctx, *gh;
    float *gxr, *gwf, *gwqkv, *gwo, *gw1, *gw2;
    unsigned char* grow; __half* gbias;
    cudaGetSymbolAddress((void**)&gx,    g_x);
    cudaGetSymbolAddress((void**)&gxn,   g_xn);
    cudaGetSymbolAddress((void**)&gqkv,  g_qkv);
    cudaGetSymbolAddress((void**)&gctx,  g_ctx);
    cudaGetSymbolAddress((void**)&gh,    g_h);
    cudaGetSymbolAddress((void**)&grow,  g_rowall);
    cudaGetSymbolAddress((void**)&gbias, g_bias);
    cudaGetSymbolAddress((void**)&gxr,   g_xr);
    cudaGetSymbolAddress((void**)&gwf,   g_wf);
    cudaGetSymbolAddress((void**)&gwqkv, g_wqkv);
    cudaGetSymbolAddress((void**)&gwo,   g_wo);
    cudaGetSymbolAddress((void**)&gw1,   g_w1);
    cudaGetSymbolAddress((void**)&gw2,   g_w2);

    cudaFuncSetAttribute((const void*)mma_gemm<0>, cudaFuncAttributeMaxDynamicSharedMemorySize, GSMB);
    cudaFuncSetAttribute((const void*)mma_gemm<1>, cudaFuncAttributeMaxDynamicSharedMemorySize, GSMB);
    cudaFuncSetAttribute((const void*)mma_gemm<2>, cudaFuncAttributeMaxDynamicSharedMemorySize, GSMB);
    cudaFuncSetAttribute((const void*)attn_mma,    cudaFuncAttributeMaxDynamicSharedMemorySize, ATTN_SMEM);

    // 0. pre-round GEMM inputs to tf32
    round_kernel<<<512, 256>>>(x,    gxr,   NTOK*INDIM/4);
    round_kernel<<<128, 256>>>(Wf,   gwf,   DM*INDIM/4);
    round_kernel<<<512, 256>>>(Wqkv, gwqkv, 3*DM*DM/4);
    round_kernel<<<256, 256>>>(Wo,   gwo,   DM*DM/4);
    round_kernel<<<512, 256>>>(W1,   gw1,   FFD*DM/4);
    round_kernel<<<512, 256>>>(W2,   gw2,   DM*FFD/4);

    // 1. row_all + fused fp16 bias prepass
    rowall_kernel<<<NTOK, 128>>>(amask, grow);
    bias_kernel<<<NTOK, 256>>>(amask, adj, grow, lscale, gbias);

    // 2. fuse projection: g_x = x @ Wf^T + bf
    mma_gemm<0><<<dim3(DM/128, NTOK/128), 256, GSMB>>>(gxr, gwf, bf, nullptr, gx, NTOK, DM, INDIM);
    // 3. LN1
    ln_kernel<<<NTOK, 128>>>(gx, ln1g, ln1b, gxn);
    // 4. qkv
    mma_gemm<0><<<dim3((3*DM)/128, NTOK/128), 256, GSMB>>>(gxn, gwqkv, bqkv, nullptr, gqkv, NTOK, 3*DM, DM);
    // 5. attention (tensor pipe, fp16 fused bias)
    attn_mma<<<dim3(LSEQ/64, NH, BB), 128, ATTN_SMEM>>>(gqkv, gbias, gctx);
    // 6. out proj + residual
    mma_gemm<2><<<dim3(DM/128, NTOK/128), 256, GSMB>>>(gctx, gwo, bo, gx, gx, NTOK, DM, DM);
    // 7. LN2
    ln_kernel<<<NTOK, 128>>>(gx, ln2g, ln2b, gxn);
    // 8. FFN up + GELU
    mma_gemm<1><<<dim3(FFD/128, NTOK/128), 256, GSMB>>>(gxn, gw1, b1, nullptr, gh, NTOK, FFD, DM);
    // 9. FFN down + residual -> out
    mma_gemm<2><<<dim3(DM/128, NTOK/128), 256, GSMB>>>(gh, gw2, b2, gx, out, NTOK, DM, FFD);
}

// round 12
// speedup vs baseline: 1.0911x; 1.0620x over previous
#include <cuda_runtime.h>
#include <math.h>
#include <stdint.h>

#define BB     4
#define LSEQ   1024
#define INDIM  256
#define DM     512
#define NH     8
#define DHD    64
#define FFD    2048
#define NTOK   (BB*LSEQ)   // 4096

// ---------------- scratch (device globals: allocation-free) ----------------
__device__ float g_x   [NTOK*DM];
__device__ float g_xn  [NTOK*DM];
__device__ float g_qkv [NTOK*3*DM];
__device__ float g_ctx [NTOK*DM];
__device__ float g_h   [NTOK*FFD];
__device__ unsigned char g_rowall[NTOK];
// tf32-pre-rounded GEMM inputs
__device__ float g_xr  [NTOK*INDIM];
__device__ float g_wf  [DM*INDIM];
__device__ float g_wqkv[3*DM*DM];
__device__ float g_wo  [DM*DM];
__device__ float g_w1  [FFD*DM];
__device__ float g_w2  [DM*FFD];

__device__ __forceinline__ uint32_t tf32r(float x) {
    uint32_t r; asm("cvt.rna.tf32.f32 %0, %1;" : "=r"(r) : "f"(x)); return r;
}
__device__ __forceinline__ float tf32f(float x) { return __uint_as_float(tf32r(x)); }
__device__ __forceinline__ void mma_tf32(float* c, const uint32_t* a, const uint32_t* b) {
    asm volatile(
        "mma.sync.aligned.m16n8k8.row.col.f32.tf32.tf32.f32 "
        "{%0,%1,%2,%3}, {%4,%5,%6,%7}, {%8,%9}, {%0,%1,%2,%3};"
        : "+f"(c[0]), "+f"(c[1]), "+f"(c[2]), "+f"(c[3])
        : "r"(a[0]), "r"(a[1]), "r"(a[2]), "r"(a[3]), "r"(b[0]), "r"(b[1]));
}
__device__ __forceinline__ uint32_t smem_u32(const void* p) {
    uint32_t a;
    asm("{ .reg .u64 t; cvta.to.shared.u64 t, %1; cvt.u32.u64 %0, t; }" : "=r"(a) : "l"(p));
    return a;
}
__device__ __forceinline__ void cpa16(uint32_t d, const void* s) {
    asm volatile("cp.async.ca.shared.global [%0], [%1], 16;" :: "r"(d), "l"(s));
}
__device__ __forceinline__ void cpa_commit() { asm volatile("cp.async.commit_group;" ::: "memory"); }
template<int N> __device__ __forceinline__ void cpa_wait() {
    asm volatile("cp.async.wait_group %0;" :: "n"(N) : "memory");
}

// ---------------- fused tf32 pre-round: all 6 tensors in one launch ----------
__global__ __launch_bounds__(256) void round_all_kernel(
    const float* __restrict__ s0, float* __restrict__ d0, int n0,   // x
    const float* __restrict__ s1, float* __restrict__ d1, int n1,   // Wf
    const float* __restrict__ s2, float* __restrict__ d2, int n2,   // Wqkv
    const float* __restrict__ s3, float* __restrict__ d3, int n3,   // Wo
    const float* __restrict__ s4, float* __restrict__ d4, int n4,   // W1
    const float* __restrict__ s5, float* __restrict__ d5, int n5)   // W2
{
    const int stride = gridDim.x * 256;
    const int base = blockIdx.x * 256 + threadIdx.x;
    #define RSEG(S, D, N) \
        for (int i = base; i < (N); i += stride) { \
            float4 v = ((const float4*)(S))[i]; \
            v.x = tf32f(v.x); v.y = tf32f(v.y); v.z = tf32f(v.z); v.w = tf32f(v.w); \
            ((float4*)(D))[i] = v; \
        }
    RSEG(s0, d0, n0) RSEG(s1, d1, n1) RSEG(s2, d2, n2)
    RSEG(s3, d3, n3) RSEG(s4, d4, n4) RSEG(s5, d5, n5)
    #undef RSEG
}

// ================= tf32 mma.sync GEMM, cp.async 2-stage (R8 proven config) ====
// C[M,N] = A[M,K] @ W[N,K]^T + bias[N]  (EPI: 0=bias, 1=+GELU(round), 2=+residual)
// Inputs pre-rounded tf32. BM=BN=128, BK=32; 8 warps 4(m)x2(n), warp tile 32x64.
#define RP   44
#define STGU (2 * 128 * RP)            // uints per stage (A then B)
#define GSMB (2 * STGU * 4)            // total dyn smem bytes (90112)

template<int EPI>
__global__ __launch_bounds__(256, 2) void mma_gemm(
    const float* __restrict__ A, const float* __restrict__ W,
    const float* __restrict__ bias, const float* __restrict__ res,
    float* __restrict__ C, int M, int N, int K)
{
    extern __shared__ uint32_t sm[];
    const uint32_t sbase = smem_u32(sm);
    const int tid = threadIdx.x;
    const int bm = blockIdx.y * 128, bn = blockIdx.x * 128;
    const int lane = tid & 31, warp = tid >> 5;
    const int wm = warp & 3, wn = warp >> 2;
    const int m_base = wm * 32, n_base = wn * 64;
    const int lg = lane >> 2, lt = lane & 3;

    float acc[2][8][4];
    #pragma unroll
    for (int mt = 0; mt < 2; mt++)
        #pragma unroll
        for (int nt = 0; nt < 8; nt++)
            #pragma unroll
            for (int q = 0; q < 4; q++) acc[mt][nt][q] = 0.f;

    const int row = tid >> 3, kc = tid & 7;
    const float* Agp = A + (size_t)(bm + row) * K + kc * 4;
    const float* Bgp = W + (size_t)(bn + row) * K + kc * 4;
    const uint32_t sA_off = (row * RP + kc * 4) * 4;
    const uint32_t rowstride = 32 * RP * 4;
    const size_t gstride = (size_t)32 * K;

    const int nc = K / 32;
    {
        uint32_t sA = sbase + sA_off;
        uint32_t sB = sA + 128 * RP * 4;
        #pragma unroll
        for (int i = 0; i < 4; i++) {
            cpa16(sA + i * rowstride, Agp + i * gstride);
            cpa16(sB + i * rowstride, Bgp + i * gstride);
        }
        cpa_commit();
    }

    for (int c = 0; c < nc; c++) {
        const int st = c & 1;
        if (c + 1 < nc) {
            uint32_t sA = sbase + ((c + 1) & 1) * (STGU * 4) + sA_off;
            uint32_t sB = sA + 128 * RP * 4;
            const float* Ag = Agp + (c + 1) * 32;
            const float* Bg = Bgp + (c + 1) * 32;
            #pragma unroll
            for (int i = 0; i < 4; i++) {
                cpa16(sA + i * rowstride, Ag + i * gstride);
                cpa16(sB + i * rowstride, Bg + i * gstride);
            }
            cpa_commit();
            cpa_wait<1>();
        } else {
            cpa_wait<0>();
        }
        __syncthreads();

        const uint32_t* As = sm + st * STGU;
        const uint32_t* Bs = As + 128 * RP;
        #pragma unroll
        for (int ks = 0; ks < 4; ks++) {
            const int k = ks * 8;
            uint32_t a[2][4], b[8][2];
            #pragma unroll
            for (int mt = 0; mt < 2; mt++) {
                const int mr = m_base + mt * 16 + lg;
                a[mt][0] = As[mr * RP + k + lt];
                a[mt][1] = As[(mr + 8) * RP + k + lt];
                a[mt][2] = As[mr * RP + k + lt + 4];
                a[mt][3] = As[(mr + 8) * RP + k + lt + 4];
            }
            #pragma unroll
            for (int nt = 0; nt < 8; nt++) {
                const int nr = n_base + nt * 8 + lg;
                b[nt][0] = Bs[nr * RP + k + lt];
                b[nt][1] = Bs[nr * RP + k + lt + 4];
            }
            #pragma unroll
            for (int mt = 0; mt < 2; mt++)
                #pragma unroll
                for (int nt = 0; nt < 8; nt++)
                    mma_tf32(acc[mt][nt], a[mt], b[nt]);
        }
        __syncthreads();
    }

    #pragma unroll
    for (int mt = 0; mt < 2; mt++) {
        #pragma unroll
        for (int nt = 0; nt < 8; nt++) {
            const int rw = bm + m_base + mt * 16 + lg;
            const int col = bn + n_base + nt * 8 + lt * 2;
            #pragma unroll
            for (int half = 0; half < 2; half++) {
                const int r = rw + half * 8;
                float v0 = acc[mt][nt][half*2+0] + bias[col];
                float v1 = acc[mt][nt][half*2+1] + bias[col+1];
                if (EPI == 1) {
                    v0 = 0.5f * v0 * (1.f + erff(v0 * 0.70710678118654752f));
                    v1 = 0.5f * v1 * (1.f + erff(v1 * 0.70710678118654752f));
                    v0 = tf32f(v0); v1 = tf32f(v1);
                }
                if (EPI == 2) {
                    float2 rr = *(const float2*)(res + (size_t)r * N + col);
                    v0 += rr.x; v1 += rr.y;
                }
                *(float2*)(C + (size_t)r * N + col) = make_float2(v0, v1);
            }
        }
    }
}

// ---------------- layernorm (tf32-rounded output) ----------------
__global__ __launch_bounds__(128) void ln_kernel(
    const float* __restrict__ X, const float* __restrict__ g,
    const float* __restrict__ b, float* __restrict__ Y)
{
    const int row = blockIdx.x;
    const int tid = threadIdx.x;
    float4 v = *(const float4*)(X + (size_t)row*DM + tid*4);
    float s  = v.x + v.y + v.z + v.w;
    float s2 = v.x*v.x + v.y*v.y + v.z*v.z + v.w*v.w;
    #pragma unroll
    for (int off = 16; off >= 1; off >>= 1) {
        s  += __shfl_xor_sync(0xffffffffu, s,  off);
        s2 += __shfl_xor_sync(0xffffffffu, s2, off);
    }
    __shared__ float sh[8];
    if ((tid & 31) == 0) { sh[tid>>5] = s; sh[4 + (tid>>5)] = s2; }
    __syncthreads();
    s  = sh[0] + sh[1] + sh[2] + sh[3];
    s2 = sh[4] + sh[5] + sh[6] + sh[7];
    float mu  = s * (1.f/DM);
    float var = s2 * (1.f/DM) - mu*mu;
    float inv = rsqrtf(var + 1e-5f);
    float4 gg = *(const float4*)(g + tid*4);
    float4 bb = *(const float4*)(b + tid*4);
    float4 y;
    y.x = tf32f((v.x - mu)*inv*gg.x + bb.x);
    y.y = tf32f((v.y - mu)*inv*gg.y + bb.y);
    y.z = tf32f((v.z - mu)*inv*gg.z + bb.z);
    y.w = tf32f((v.w - mu)*inv*gg.w + bb.w);
    *(float4*)(Y + (size_t)row*DM + tid*4) = y;
}

// ---------------- row_all (mask int32 0/1) ----------------
__global__ __launch_bounds__(128) void rowall_kernel(
    const int* __restrict__ mask, unsigned char* __restrict__ out)
{
    const int row = blockIdx.x;
    const int tid = threadIdx.x;
    const int* m = mask + (size_t)row * LSEQ;
    int mn = 1;
    #pragma unroll
    for (int c = 0; c < LSEQ / 512; c++) {
        int4 v = *(const int4*)(m + c*512 + tid*4);
        mn = min(mn, min(min(v.x, v.y), min(v.z, v.w)));
    }
    #pragma unroll
    for (int off = 16; off >= 1; off >>= 1)
        mn = min(mn, __shfl_xor_sync(0xffffffffu, mn, off));
    __shared__ int sh[4];
    if ((tid & 31) == 0) sh[tid>>5] = mn;
    __syncthreads();
    if (tid == 0) {
        int r = min(min(sh[0], sh[1]), min(sh[2], sh[3]));
        out[row] = (r != 0) ? 1 : 0;
    }
}

// ---------------- flash attention on tensor pipe (tf32 mma.sync, R8 form) ----
#define APAD 68
#define VPAD 72
#define SM_Q 0
#define SM_K (64*APAD)
#define SM_P (2*64*APAD)
#define SM_V (3*64*APAD)
#define ATTN_SMEM ((3*64*APAD + 64*VPAD) * 4)

__global__ __launch_bounds__(128) void attn_mma(
    const float* __restrict__ qkv,
    const int* __restrict__ mask,
    const float* __restrict__ adj,
    const unsigned char* __restrict__ rowall,
    const float* __restrict__ logscale,
    float* __restrict__ ctx)
{
    extern __shared__ uint32_t sm[];
    uint32_t* Qs = sm + SM_Q;
    uint32_t* Ks = sm + SM_K;
    uint32_t* Ps = sm + SM_P;
    uint32_t* Vs = sm + SM_V;

    const int b = blockIdx.z, h = blockIdx.y;
    const int q0 = blockIdx.x * 64;
    const int tid = threadIdx.x;
    const int lane = tid & 31, warp = tid >> 5;
    const int lg = lane >> 2, lt = lane & 3;
    const int mb = warp * 16;
    const float escale = expf(logscale[0]);

    const int lrow = tid >> 1, lcb = (tid & 1) * 32;

    {
        const float* qg = qkv + (size_t)(b*LSEQ + q0 + lrow)*(3*DM) + h*DHD + lcb;
        #pragma unroll
        for (int i = 0; i < 8; i++) {
            float4 v = *(const float4*)(qg + i*4);
            uint32_t* dst = Qs + lrow*APAD + lcb + i*4;
            dst[0] = tf32r(v.x); dst[1] = tf32r(v.y);
            dst[2] = tf32r(v.z); dst[3] = tf32r(v.w);
        }
    }
    __syncthreads();

    uint32_t qa[8][4];
    #pragma unroll
    for (int ks = 0; ks < 8; ks++) {
        const int k8 = ks * 8;
        qa[ks][0] = Qs[(mb+lg  )*APAD + k8 + lt];
        qa[ks][1] = Qs[(mb+lg+8)*APAD + k8 + lt];
        qa[ks][2] = Qs[(mb+lg  )*APAD + k8 + lt + 4];
        qa[ks][3] = Qs[(mb+lg+8)*APAD + k8 + lt + 4];
    }

    float o[8][4];
    #pragma unroll
    for (int nt = 0; nt < 8; nt++)
        #pragma unroll
        for (int q = 0; q < 4; q++) o[nt][q] = 0.f;
    float mi[2] = {-1e30f, -1e30f}, li[2] = {0.f, 0.f};

    const int qrow[2] = { q0 + mb + lg, q0 + mb + lg + 8 };
    const bool raq[2] = { rowall[b*LSEQ + qrow[0]] != 0, rowall[b*LSEQ + qrow[1]] != 0 };

    for (int k0 = 0; k0 < LSEQ; k0 += 64) {
        {
            const float* kg = qkv + (size_t)(b*LSEQ + k0 + lrow)*(3*DM) + DM + h*DHD + lcb;
            const float* vg = kg + DM;
            #pragma unroll
            for (int i = 0; i < 8; i++) {
                float4 kv = *(const float4*)(kg + i*4);
                uint32_t* kd = Ks + lrow*APAD + lcb + i*4;
                kd[0] = tf32r(kv.x); kd[1] = tf32r(kv.y);
                kd[2] = tf32r(kv.z); kd[3] = tf32r(kv.w);
                float4 vv = *(const float4*)(vg + i*4);
                uint32_t* vd = Vs + lrow*VPAD + lcb + i*4;
                vd[0] = tf32r(vv.x); vd[1] = tf32r(vv.y);
                vd[2] = tf32r(vv.z); vd[3] = tf32r(vv.w);
            }
        }
        __syncthreads();

        float s[8][4];
        #pragma unroll
        for (int nt = 0; nt < 8; nt++)
            #pragma unroll
            for (int q = 0; q < 4; q++) s[nt][q] = 0.f;
        #pragma unroll
        for (int ks = 0; ks < 8; ks++) {
            const int k8 = ks * 8;
            #pragma unroll
            for (int nt = 0; nt < 8; nt++) {
                uint32_t bfr[2];
                bfr[0] = Ks[(nt*8+lg)*APAD + k8 + lt];
                bfr[1] = Ks[(nt*8+lg)*APAD + k8 + lt + 4];
                mma_tf32(s[nt], qa[ks], bfr);
            }
        }

        #pragma unroll
        for (int r = 0; r < 2; r++) {
            const int q = qrow[r];
            const size_t roff = ((size_t)b*LSEQ + q)*LSEQ + k0;
            float rmax = -1e30f;
            #pragma unroll
            for (int nt = 0; nt < 8; nt++) {
                const int col = nt*8 + lt*2;
                const int2 mm = *(const int2*)(mask + roff + col);
                const float2 ad = *(const float2*)(adj + roff + col);
                float a0 = fminf(fmaxf(ad.x, 0.f), 1.f);
                float a1 = fminf(fmaxf(ad.y, 0.f), 1.f);
                bool e0 = (mm.x != 0) && !((k0+col   == q) && raq[r]);
                bool e1 = (mm.y != 0) && !((k0+col+1 == q) && raq[r]);
                float v0 = s[nt][2*r  ]*0.125f + (e0 ? -10000.f : 0.f) + escale*a0;
                float v1 = s[nt][2*r+1]*0.125f + (e1 ? -10000.f : 0.f) + escale*a1;
                s[nt][2*r  ] = v0; s[nt][2*r+1] = v1;
                rmax = fmaxf(rmax, fmaxf(v0, v1));
            }
            rmax = fmaxf(rmax, __shfl_xor_sync(0xffffffffu, rmax, 1));
            rmax = fmaxf(rmax, __shfl_xor_sync(0xffffffffu, rmax, 2));
            float mnew = fmaxf(mi[r], rmax);
            float corr = __expf(mi[r] - mnew);
            float psum = 0.f;
            #pragma unroll
            for (int nt = 0; nt < 8; nt++) {
                float p0 = __expf(s[nt][2*r  ] - mnew);
                float p1 = __expf(s[nt][2*r+1] - mnew);
                s[nt][2*r] = p0; s[nt][2*r+1] = p1;
                psum += p0 + p1;
            }
            psum += __shfl_xor_sync(0xffffffffu, psum, 1);
            psum += __shfl_xor_sync(0xffffffffu, psum, 2);
            li[r] = li[r]*corr + psum;
            mi[r] = mnew;
            #pragma unroll
            for (int nt = 0; nt < 8; nt++) { o[nt][2*r] *= corr; o[nt][2*r+1] *= corr; }
            #pragma unroll
            for (int nt = 0; nt < 8; nt++) {
                uint32_t* pd = Ps + (mb+lg+8*r)*APAD + nt*8 + lt*2;
                pd[0] = tf32r(s[nt][2*r]); pd[1] = tf32r(s[nt][2*r+1]);
            }
        }
        __syncthreads();

        #pragma unroll
        for (int ks = 0; ks < 8; ks++) {
            const int k8 = ks * 8;
            uint32_t pa[4];
            pa[0] = Ps[(mb+lg  )*APAD + k8 + lt];
            pa[1] = Ps[(mb+lg+8)*APAD + k8 + lt];
            pa[2] = Ps[(mb+lg  )*APAD + k8 + lt + 4];
            pa[3] = Ps[(mb+lg+8)*APAD + k8 + lt + 4];
            #pragma unroll
            for (int nt = 0; nt < 8; nt++) {
                uint32_t bfr[2];
                bfr[0] = Vs[(k8+lt  )*VPAD + nt*8 + lg];
                bfr[1] = Vs[(k8+lt+4)*VPAD + nt*8 + lg];
                mma_tf32(o[nt], pa, bfr);
            }
        }
        __syncthreads();
    }

    const float inv0 = 1.f / li[0], inv1 = 1.f / li[1];
    #pragma unroll
    for (int nt = 0; nt < 8; nt++) {
        const int col = h*DHD + nt*8 + lt*2;
        *(float2*)(ctx + (size_t)(b*LSEQ + qrow[0])*DM + col) =
            make_float2(tf32f(o[nt][0]*inv0), tf32f(o[nt][1]*inv0));
        *(float2*)(ctx + (size_t)(b*LSEQ + qrow[1])*DM + col) =
            make_float2(tf32f(o[nt][2]*inv1), tf32f(o[nt][3]*inv1));
    }
}

// ---------------- launch ----------------
extern "C" void kernel_launch(void* const* d_in, const int* in_sizes, int n_in,
                              void* d_out, int out_size)
{
    (void)in_sizes; (void)n_in; (void)out_size;
    const float* x      = (const float*)d_in[0];
    const int*   amask  = (const int*)d_in[1];
    const float* adj    = (const float*)d_in[2];
    const float* Wf     = (const float*)d_in[3];
    const float* bf     = (const float*)d_in[4];
    const float* Wqkv   = (const float*)d_in[5];
    const float* bqkv   = (const float*)d_in[6];
    const float* Wo     = (const float*)d_in[7];
    const float* bo     = (const float*)d_in[8];
    const float* ln1g   = (const float*)d_in[9];
    const float* ln1b   = (const float*)d_in[10];
    const float* ln2g   = (const float*)d_in[11];
    const float* ln2b   = (const float*)d_in[12];
    const float* W1     = (const float*)d_in[13];
    const float* b1     = (const float*)d_in[14];
    const float* W2     = (const float*)d_in[15];
    const float* b2     = (const float*)d_in[16];
    const float* lscale = (const float*)d_in[17];
    float* out = (float*)d_out;

    float *gx, *gxn, *gqkv, *gctx, *gh;
    float *gxr, *gwf, *gwqkv, *gwo, *gw1, *gw2;
    unsigned char* grow;
    cudaGetSymbolAddress((void**)&gx,    g_x);
    cudaGetSymbolAddress((void**)&gxn,   g_xn);
    cudaGetSymbolAddress((void**)&gqkv,  g_qkv);
    cudaGetSymbolAddress((void**)&gctx,  g_ctx);
    cudaGetSymbolAddress((void**)&gh,    g_h);
    cudaGetSymbolAddress((void**)&grow,  g_rowall);
    cudaGetSymbolAddress((void**)&gxr,   g_xr);
    cudaGetSymbolAddress((void**)&gwf,   g_wf);
    cudaGetSymbolAddress((void**)&gwqkv, g_wqkv);
    cudaGetSymbolAddress((void**)&gwo,   g_wo);
    cudaGetSymbolAddress((void**)&gw1,   g_w1);
    cudaGetSymbolAddress((void**)&gw2,   g_w2);

    cudaFuncSetAttribute((const void*)mma_gemm<0>, cudaFuncAttributeMaxDynamicSharedMemorySize, GSMB);
    cudaFuncSetAttribute((const void*)mma_gemm<1>, cudaFuncAttributeMaxDynamicSharedMemorySize, GSMB);
    cudaFuncSetAttribute((const void*)mma_gemm<2>, cudaFuncAttributeMaxDynamicSharedMemorySize, GSMB);
    cudaFuncSetAttribute((const void*)attn_mma,    cudaFuncAttributeMaxDynamicSharedMemorySize, ATTN_SMEM);

    // 0. ONE fused pre-round launch: x + all 5 weights -> tf32 (RNA)
    round_all_kernel<<<592, 256>>>(
        x,    gxr,   NTOK*INDIM/4,
        Wf,   gwf,   DM*INDIM/4,
        Wqkv, gwqkv, 3*DM*DM/4,
        Wo,   gwo,   DM*DM/4,
        W1,   gw1,   FFD*DM/4,
        W2,   gw2,   DM*FFD/4);

    // 1. row_all
    rowall_kernel<<<NTOK, 128>>>(amask, grow);
    // 2. fuse projection: g_x = x @ Wf^T + bf
    mma_gemm<0><<<dim3(DM/128, NTOK/128), 256, GSMB>>>(gxr, gwf, bf, nullptr, gx, NTOK, DM, INDIM);
    // 3. LN1
    ln_kernel<<<NTOK, 128>>>(gx, ln1g, ln1b, gxn);
    // 4. qkv
    mma_gemm<0><<<dim3((3*DM)/128, NTOK/128), 256, GSMB>>>(gxn, gwqkv, bqkv, nullptr, gqkv, NTOK, 3*DM, DM);
    // 5. attention (tensor pipe, inline mask/adj)
    attn_mma<<<dim3(LSEQ/64, NH, BB), 128, ATTN_SMEM>>>(gqkv, amask, adj, grow, lscale, gctx);
    // 6. out proj + residual
    mma_gemm<2><<<dim3(DM/128, NTOK/128), 256, GSMB>>>(gctx, gwo, bo, gx, gx, NTOK, DM, DM);
    // 7. LN2
    ln_kernel<<<NTOK, 128>>>(gx, ln2g, ln2b, gxn);
    // 8. FFN up + GELU
    mma_gemm<1><<<dim3(FFD/128, NTOK/128), 256, GSMB>>>(gxn, gw1, b1, nullptr, gh, NTOK, FFD, DM);
    // 9. FFN down + residual -> out
    mma_gemm<2><<<dim3(DM/128, NTOK/128), 256, GSMB>>>(gh, gw2, b2, gx, out, NTOK, DM, FFD);
}

// round 13
// speedup vs baseline: 1.2032x; 1.1027x over previous
#include <cuda_runtime.h>
#include <math.h>
#include <stdint.h>

#define BB     4
#define LSEQ   1024
#define INDIM  256
#define DM     512
#define NH     8
#define DHD    64
#define FFD    2048
#define NTOK   (BB*LSEQ)   // 4096

// ---------------- scratch (device globals: allocation-free) ----------------
__device__ float g_x   [NTOK*DM];
__device__ float g_xn  [NTOK*DM];
__device__ float g_qkv [NTOK*3*DM];
__device__ float g_ctx [NTOK*DM];
__device__ float g_h   [NTOK*FFD];
__device__ unsigned char g_rowall[NTOK];
// tf32-pre-rounded GEMM inputs
__device__ float g_xr  [NTOK*INDIM];
__device__ float g_wf  [DM*INDIM];
__device__ float g_wqkv[3*DM*DM];
__device__ float g_wo  [DM*DM];
__device__ float g_w1  [FFD*DM];
__device__ float g_w2  [DM*FFD];

__device__ __forceinline__ uint32_t tf32r(float x) {
    uint32_t r; asm("cvt.rna.tf32.f32 %0, %1;" : "=r"(r) : "f"(x)); return r;
}
__device__ __forceinline__ float tf32f(float x) { return __uint_as_float(tf32r(x)); }
__device__ __forceinline__ void mma_tf32(float* c, const uint32_t* a, const uint32_t* b) {
    asm volatile(
        "mma.sync.aligned.m16n8k8.row.col.f32.tf32.tf32.f32 "
        "{%0,%1,%2,%3}, {%4,%5,%6,%7}, {%8,%9}, {%0,%1,%2,%3};"
        : "+f"(c[0]), "+f"(c[1]), "+f"(c[2]), "+f"(c[3])
        : "r"(a[0]), "r"(a[1]), "r"(a[2]), "r"(a[3]), "r"(b[0]), "r"(b[1]));
}
__device__ __forceinline__ uint32_t smem_u32(const void* p) {
    uint32_t a;
    asm("{ .reg .u64 t; cvta.to.shared.u64 t, %1; cvt.u32.u64 %0, t; }" : "=r"(a) : "l"(p));
    return a;
}
__device__ __forceinline__ void cpa16(uint32_t d, const void* s) {
    asm volatile("cp.async.ca.shared.global [%0], [%1], 16;" :: "r"(d), "l"(s));
}
__device__ __forceinline__ void cpa_commit() { asm volatile("cp.async.commit_group;" ::: "memory"); }
template<int N> __device__ __forceinline__ void cpa_wait() {
    asm volatile("cp.async.wait_group %0;" :: "n"(N) : "memory");
}

// ---------------- fused tf32 pre-round: all 6 tensors in one launch ----------
__global__ __launch_bounds__(256) void round_all_kernel(
    const float* __restrict__ s0, float* __restrict__ d0, int n0,
    const float* __restrict__ s1, float* __restrict__ d1, int n1,
    const float* __restrict__ s2, float* __restrict__ d2, int n2,
    const float* __restrict__ s3, float* __restrict__ d3, int n3,
    const float* __restrict__ s4, float* __restrict__ d4, int n4,
    const float* __restrict__ s5, float* __restrict__ d5, int n5)
{
    const int stride = gridDim.x * 256;
    const int base = blockIdx.x * 256 + threadIdx.x;
    #define RSEG(S, D, N) \
        for (int i = base; i < (N); i += stride) { \
            float4 v = ((const float4*)(S))[i]; \
            v.x = tf32f(v.x); v.y = tf32f(v.y); v.z = tf32f(v.z); v.w = tf32f(v.w); \
            ((float4*)(D))[i] = v; \
        }
    RSEG(s0, d0, n0) RSEG(s1, d1, n1) RSEG(s2, d2, n2)
    RSEG(s3, d3, n3) RSEG(s4, d4, n4) RSEG(s5, d5, n5)
    #undef RSEG
}

// ================= tf32 mma.sync GEMM, cp.async 2-stage (R8 proven config) ====
#define RP   44
#define STGU (2 * 128 * RP)
#define GSMB (2 * STGU * 4)

template<int EPI>
__global__ __launch_bounds__(256, 2) void mma_gemm(
    const float* __restrict__ A, const float* __restrict__ W,
    const float* __restrict__ bias, const float* __restrict__ res,
    float* __restrict__ C, int M, int N, int K)
{
    extern __shared__ uint32_t sm[];
    const uint32_t sbase = smem_u32(sm);
    const int tid = threadIdx.x;
    const int bm = blockIdx.y * 128, bn = blockIdx.x * 128;
    const int lane = tid & 31, warp = tid >> 5;
    const int wm = warp & 3, wn = warp >> 2;
    const int m_base = wm * 32, n_base = wn * 64;
    const int lg = lane >> 2, lt = lane & 3;

    float acc[2][8][4];
    #pragma unroll
    for (int mt = 0; mt < 2; mt++)
        #pragma unroll
        for (int nt = 0; nt < 8; nt++)
            #pragma unroll
            for (int q = 0; q < 4; q++) acc[mt][nt][q] = 0.f;

    const int row = tid >> 3, kc = tid & 7;
    const float* Agp = A + (size_t)(bm + row) * K + kc * 4;
    const float* Bgp = W + (size_t)(bn + row) * K + kc * 4;
    const uint32_t sA_off = (row * RP + kc * 4) * 4;
    const uint32_t rowstride = 32 * RP * 4;
    const size_t gstride = (size_t)32 * K;

    const int nc = K / 32;
    {
        uint32_t sA = sbase + sA_off;
        uint32_t sB = sA + 128 * RP * 4;
        #pragma unroll
        for (int i = 0; i < 4; i++) {
            cpa16(sA + i * rowstride, Agp + i * gstride);
            cpa16(sB + i * rowstride, Bgp + i * gstride);
        }
        cpa_commit();
    }

    for (int c = 0; c < nc; c++) {
        const int st = c & 1;
        if (c + 1 < nc) {
            uint32_t sA = sbase + ((c + 1) & 1) * (STGU * 4) + sA_off;
            uint32_t sB = sA + 128 * RP * 4;
            const float* Ag = Agp + (c + 1) * 32;
            const float* Bg = Bgp + (c + 1) * 32;
            #pragma unroll
            for (int i = 0; i < 4; i++) {
                cpa16(sA + i * rowstride, Ag + i * gstride);
                cpa16(sB + i * rowstride, Bg + i * gstride);
            }
            cpa_commit();
            cpa_wait<1>();
        } else {
            cpa_wait<0>();
        }
        __syncthreads();

        const uint32_t* As = sm + st * STGU;
        const uint32_t* Bs = As + 128 * RP;
        #pragma unroll
        for (int ks = 0; ks < 4; ks++) {
            const int k = ks * 8;
            uint32_t a[2][4], b[8][2];
            #pragma unroll
            for (int mt = 0; mt < 2; mt++) {
                const int mr = m_base + mt * 16 + lg;
                a[mt][0] = As[mr * RP + k + lt];
                a[mt][1] = As[(mr + 8) * RP + k + lt];
                a[mt][2] = As[mr * RP + k + lt + 4];
                a[mt][3] = As[(mr + 8) * RP + k + lt + 4];
            }
            #pragma unroll
            for (int nt = 0; nt < 8; nt++) {
                const int nr = n_base + nt * 8 + lg;
                b[nt][0] = Bs[nr * RP + k + lt];
                b[nt][1] = Bs[nr * RP + k + lt + 4];
            }
            #pragma unroll
            for (int mt = 0; mt < 2; mt++)
                #pragma unroll
                for (int nt = 0; nt < 8; nt++)
                    mma_tf32(acc[mt][nt], a[mt], b[nt]);
        }
        __syncthreads();
    }

    #pragma unroll
    for (int mt = 0; mt < 2; mt++) {
        #pragma unroll
        for (int nt = 0; nt < 8; nt++) {
            const int rw = bm + m_base + mt * 16 + lg;
            const int col = bn + n_base + nt * 8 + lt * 2;
            #pragma unroll
            for (int half = 0; half < 2; half++) {
                const int r = rw + half * 8;
                float v0 = acc[mt][nt][half*2+0] + bias[col];
                float v1 = acc[mt][nt][half*2+1] + bias[col+1];
                if (EPI == 1) {
                    v0 = 0.5f * v0 * (1.f + erff(v0 * 0.70710678118654752f));
                    v1 = 0.5f * v1 * (1.f + erff(v1 * 0.70710678118654752f));
                    v0 = tf32f(v0); v1 = tf32f(v1);
                }
                if (EPI == 2) {
                    float2 rr = *(const float2*)(res + (size_t)r * N + col);
                    v0 += rr.x; v1 += rr.y;
                }
                *(float2*)(C + (size_t)r * N + col) = make_float2(v0, v1);
            }
        }
    }
}

// ---------------- layernorm (tf32-rounded output) ----------------
__global__ __launch_bounds__(128) void ln_kernel(
    const float* __restrict__ X, const float* __restrict__ g,
    const float* __restrict__ b, float* __restrict__ Y)
{
    const int row = blockIdx.x;
    const int tid = threadIdx.x;
    float4 v = *(const float4*)(X + (size_t)row*DM + tid*4);
    float s  = v.x + v.y + v.z + v.w;
    float s2 = v.x*v.x + v.y*v.y + v.z*v.z + v.w*v.w;
    #pragma unroll
    for (int off = 16; off >= 1; off >>= 1) {
        s  += __shfl_xor_sync(0xffffffffu, s,  off);
        s2 += __shfl_xor_sync(0xffffffffu, s2, off);
    }
    __shared__ float sh[8];
    if ((tid & 31) == 0) { sh[tid>>5] = s; sh[4 + (tid>>5)] = s2; }
    __syncthreads();
    s  = sh[0] + sh[1] + sh[2] + sh[3];
    s2 = sh[4] + sh[5] + sh[6] + sh[7];
    float mu  = s * (1.f/DM);
    float var = s2 * (1.f/DM) - mu*mu;
    float inv = rsqrtf(var + 1e-5f);
    float4 gg = *(const float4*)(g + tid*4);
    float4 bb = *(const float4*)(b + tid*4);
    float4 y;
    y.x = tf32f((v.x - mu)*inv*gg.x + bb.x);
    y.y = tf32f((v.y - mu)*inv*gg.y + bb.y);
    y.z = tf32f((v.z - mu)*inv*gg.z + bb.z);
    y.w = tf32f((v.w - mu)*inv*gg.w + bb.w);
    *(float4*)(Y + (size_t)row*DM + tid*4) = y;
}

// ---------------- row_all (mask int32 0/1) ----------------
__global__ __launch_bounds__(128) void rowall_kernel(
    const int* __restrict__ mask, unsigned char* __restrict__ out)
{
    const int row = blockIdx.x;
    const int tid = threadIdx.x;
    const int* m = mask + (size_t)row * LSEQ;
    int mn = 1;
    #pragma unroll
    for (int c = 0; c < LSEQ / 512; c++) {
        int4 v = *(const int4*)(m + c*512 + tid*4);
        mn = min(mn, min(min(v.x, v.y), min(v.z, v.w)));
    }
    #pragma unroll
    for (int off = 16; off >= 1; off >>= 1)
        mn = min(mn, __shfl_xor_sync(0xffffffffu, mn, off));
    __shared__ int sh[4];
    if ((tid & 31) == 0) sh[tid>>5] = mn;
    __syncthreads();
    if (tid == 0) {
        int r = min(min(sh[0], sh[1]), min(sh[2], sh[3]));
        out[row] = (r != 0) ? 1 : 0;
    }
}

// ---------------- flash attention: 128q CTA, 8 warps, Ps overlays Qs ---------
// grid (L/128, H, B) = 256 CTAs, 256 threads. K-tile 64. Warp = 16q x 64k.
// smem: QP[128][68] (Q then P), K[64][68], V[64][72] = 70656 B -> 3 CTAs/SM.
#define APAD 68
#define VPAD 72
#define SM_QP 0
#define SM_K  (128*APAD)
#define SM_V  (128*APAD + 64*APAD)
#define ATTN_SMEM ((128*APAD + 64*APAD + 64*VPAD) * 4)

__global__ __launch_bounds__(256) void attn_mma(
    const float* __restrict__ qkv,
    const int* __restrict__ mask,
    const float* __restrict__ adj,
    const unsigned char* __restrict__ rowall,
    const float* __restrict__ logscale,
    float* __restrict__ ctx)
{
    extern __shared__ uint32_t sm[];
    uint32_t* QPs = sm + SM_QP;   // Q tile, later reused as P
    uint32_t* Ks  = sm + SM_K;
    uint32_t* Vs  = sm + SM_V;

    const int b = blockIdx.z, h = blockIdx.y;
    const int q0 = blockIdx.x * 128;
    const int tid = threadIdx.x;
    const int lane = tid & 31, warp = tid >> 5;
    const int lg = lane >> 2, lt = lane & 3;
    const int mb = warp * 16;                 // 8 warps x 16 q-rows = 128
    const float escale = expf(logscale[0]);

    // ---- load Q tile (128 rows, 2 threads/row, 32 cols each) ----
    {
        const int lrow = tid >> 1, lcb = (tid & 1) * 32;
        const float* qg = qkv + (size_t)(b*LSEQ + q0 + lrow)*(3*DM) + h*DHD + lcb;
        #pragma unroll
        for (int i = 0; i < 8; i++) {
            float4 v = *(const float4*)(qg + i*4);
            uint32_t* dst = QPs + lrow*APAD + lcb + i*4;
            dst[0] = tf32r(v.x); dst[1] = tf32r(v.y);
            dst[2] = tf32r(v.z); dst[3] = tf32r(v.w);
        }
    }
    __syncthreads();

    // ---- hoist Q fragments (Qs smem dead afterwards -> reused as P) ----
    uint32_t qa[8][4];
    #pragma unroll
    for (int ks = 0; ks < 8; ks++) {
        const int k8 = ks * 8;
        qa[ks][0] = QPs[(mb+lg  )*APAD + k8 + lt];
        qa[ks][1] = QPs[(mb+lg+8)*APAD + k8 + lt];
        qa[ks][2] = QPs[(mb+lg  )*APAD + k8 + lt + 4];
        qa[ks][3] = QPs[(mb+lg+8)*APAD + k8 + lt + 4];
    }

    float o[8][4];
    #pragma unroll
    for (int nt = 0; nt < 8; nt++)
        #pragma unroll
        for (int q = 0; q < 4; q++) o[nt][q] = 0.f;
    float mi[2] = {-1e30f, -1e30f}, li[2] = {0.f, 0.f};

    const int qrow[2] = { q0 + mb + lg, q0 + mb + lg + 8 };
    const bool raq[2] = { rowall[b*LSEQ + qrow[0]] != 0, rowall[b*LSEQ + qrow[1]] != 0 };

    // K loaded by threads 0-127, V by threads 128-255 (warp-granular split)
    const int lhalf = tid >> 7;
    const int lt128 = tid & 127;
    const int lrow = lt128 >> 1, lcb = (lt128 & 1) * 32;

    for (int k0 = 0; k0 < LSEQ; k0 += 64) {
        if (lhalf == 0) {
            const float* kg = qkv + (size_t)(b*LSEQ + k0 + lrow)*(3*DM) + DM + h*DHD + lcb;
            #pragma unroll
            for (int i = 0; i < 8; i++) {
                float4 kv = *(const float4*)(kg + i*4);
                uint32_t* kd = Ks + lrow*APAD + lcb + i*4;
                kd[0] = tf32r(kv.x); kd[1] = tf32r(kv.y);
                kd[2] = tf32r(kv.z); kd[3] = tf32r(kv.w);
            }
        } else {
            const float* vg = qkv + (size_t)(b*LSEQ + k0 + lrow)*(3*DM) + 2*DM + h*DHD + lcb;
            #pragma unroll
            for (int i = 0; i < 8; i++) {
                float4 vv = *(const float4*)(vg + i*4);
                uint32_t* vd = Vs + lrow*VPAD + lcb + i*4;
                vd[0] = tf32r(vv.x); vd[1] = tf32r(vv.y);
                vd[2] = tf32r(vv.z); vd[3] = tf32r(vv.w);
            }
        }
        __syncthreads();

        // ---- S = Q @ K^T ----
        float s[8][4];
        #pragma unroll
        for (int nt = 0; nt < 8; nt++)
            #pragma unroll
            for (int q = 0; q < 4; q++) s[nt][q] = 0.f;
        #pragma unroll
        for (int ks = 0; ks < 8; ks++) {
            const int k8 = ks * 8;
            #pragma unroll
            for (int nt = 0; nt < 8; nt++) {
                uint32_t bfr[2];
                bfr[0] = Ks[(nt*8+lg)*APAD + k8 + lt];
                bfr[1] = Ks[(nt*8+lg)*APAD + k8 + lt + 4];
                mma_tf32(s[nt], qa[ks], bfr);
            }
        }

        // ---- bias + online softmax (rows lg, lg+8; warp-local) ----
        #pragma unroll
        for (int r = 0; r < 2; r++) {
            const int q = qrow[r];
            const size_t roff = ((size_t)b*LSEQ + q)*LSEQ + k0;
            float rmax = -1e30f;
            #pragma unroll
            for (int nt = 0; nt < 8; nt++) {
                const int col = nt*8 + lt*2;
                const int2 mm = *(const int2*)(mask + roff + col);
                const float2 ad = *(const float2*)(adj + roff + col);
                float a0 = fminf(fmaxf(ad.x, 0.f), 1.f);
                float a1 = fminf(fmaxf(ad.y, 0.f), 1.f);
                bool e0 = (mm.x != 0) && !((k0+col   == q) && raq[r]);
                bool e1 = (mm.y != 0) && !((k0+col+1 == q) && raq[r]);
                float v0 = s[nt][2*r  ]*0.125f + (e0 ? -10000.f : 0.f) + escale*a0;
                float v1 = s[nt][2*r+1]*0.125f + (e1 ? -10000.f : 0.f) + escale*a1;
                s[nt][2*r  ] = v0; s[nt][2*r+1] = v1;
                rmax = fmaxf(rmax, fmaxf(v0, v1));
            }
            rmax = fmaxf(rmax, __shfl_xor_sync(0xffffffffu, rmax, 1));
            rmax = fmaxf(rmax, __shfl_xor_sync(0xffffffffu, rmax, 2));
            float mnew = fmaxf(mi[r], rmax);
            float corr = __expf(mi[r] - mnew);
            float psum = 0.f;
            #pragma unroll
            for (int nt = 0; nt < 8; nt++) {
                float p0 = __expf(s[nt][2*r  ] - mnew);
                float p1 = __expf(s[nt][2*r+1] - mnew);
                s[nt][2*r] = p0; s[nt][2*r+1] = p1;
                psum += p0 + p1;
            }
            psum += __shfl_xor_sync(0xffffffffu, psum, 1);
            psum += __shfl_xor_sync(0xffffffffu, psum, 2);
            li[r] = li[r]*corr + psum;
            mi[r] = mnew;
            #pragma unroll
            for (int nt = 0; nt < 8; nt++) { o[nt][2*r] *= corr; o[nt][2*r+1] *= corr; }
            // stash P (warp-local rows, overlaying Q smem)
            #pragma unroll
            for (int nt = 0; nt < 8; nt++) {
                uint32_t* pd = QPs + (mb+lg+8*r)*APAD + nt*8 + lt*2;
                pd[0] = tf32r(s[nt][2*r]); pd[1] = tf32r(s[nt][2*r+1]);
            }
        }
        __syncwarp();   // P rows are warp-local; warp-level visibility suffices

        // ---- O += P @ V ----
        #pragma unroll
        for (int ks = 0; ks < 8; ks++) {
            const int k8 = ks * 8;
            uint32_t pa[4];
            pa[0] = QPs[(mb+lg  )*APAD + k8 + lt];
            pa[1] = QPs[(mb+lg+8)*APAD + k8 + lt];
            pa[2] = QPs[(mb+lg  )*APAD + k8 + lt + 4];
            pa[3] = QPs[(mb+lg+8)*APAD + k8 + lt + 4];
            #pragma unroll
            for (int nt = 0; nt < 8; nt++) {
                uint32_t bfr[2];
                bfr[0] = Vs[(k8+lt  )*VPAD + nt*8 + lg];
                bfr[1] = Vs[(k8+lt+4)*VPAD + nt*8 + lg];
                mma_tf32(o[nt], pa, bfr);
            }
        }
        __syncthreads();   // before next tile overwrites Ks/Vs
    }

    const float inv0 = 1.f / li[0], inv1 = 1.f / li[1];
    #pragma unroll
    for (int nt = 0; nt < 8; nt++) {
        const int col = h*DHD + nt*8 + lt*2;
        *(float2*)(ctx + (size_t)(b*LSEQ + qrow[0])*DM + col) =
            make_float2(tf32f(o[nt][0]*inv0), tf32f(o[nt][1]*inv0));
        *(float2*)(ctx + (size_t)(b*LSEQ + qrow[1])*DM + col) =
            make_float2(tf32f(o[nt][2]*inv1), tf32f(o[nt][3]*inv1));
    }
}

// ---------------- launch ----------------
extern "C" void kernel_launch(void* const* d_in, const int* in_sizes, int n_in,
                              void* d_out, int out_size)
{
    (void)in_sizes; (void)n_in; (void)out_size;
    const float* x      = (const float*)d_in[0];
    const int*   amask  = (const int*)d_in[1];
    const float* adj    = (const float*)d_in[2];
    const float* Wf     = (const float*)d_in[3];
    const float* bf     = (const float*)d_in[4];
    const float* Wqkv   = (const float*)d_in[5];
    const float* bqkv   = (const float*)d_in[6];
    const float* Wo     = (const float*)d_in[7];
    const float* bo     = (const float*)d_in[8];
    const float* ln1g   = (const float*)d_in[9];
    const float* ln1b   = (const float*)d_in[10];
    const float* ln2g   = (const float*)d_in[11];
    const float* ln2b   = (const float*)d_in[12];
    const float* W1     = (const float*)d_in[13];
    const float* b1     = (const float*)d_in[14];
    const float* W2     = (const float*)d_in[15];
    const float* b2     = (const float*)d_in[16];
    const float* lscale = (const float*)d_in[17];
    float* out = (float*)d_out;

    float *gx, *gxn, *gqkv, *gctx, *gh;
    float *gxr, *gwf, *gwqkv, *gwo, *gw1, *gw2;
    unsigned char* grow;
    cudaGetSymbolAddress((void**)&gx,    g_x);
    cudaGetSymbolAddress((void**)&gxn,   g_xn);
    cudaGetSymbolAddress((void**)&gqkv,  g_qkv);
    cudaGetSymbolAddress((void**)&gctx,  g_ctx);
    cudaGetSymbolAddress((void**)&gh,    g_h);
    cudaGetSymbolAddress((void**)&grow,  g_rowall);
    cudaGetSymbolAddress((void**)&gxr,   g_xr);
    cudaGetSymbolAddress((void**)&gwf,   g_wf);
    cudaGetSymbolAddress((void**)&gwqkv, g_wqkv);
    cudaGetSymbolAddress((void**)&gwo,   g_wo);
    cudaGetSymbolAddress((void**)&gw1,   g_w1);
    cudaGetSymbolAddress((void**)&gw2,   g_w2);

    cudaFuncSetAttribute((const void*)mma_gemm<0>, cudaFuncAttributeMaxDynamicSharedMemorySize, GSMB);
    cudaFuncSetAttribute((const void*)mma_gemm<1>, cudaFuncAttributeMaxDynamicSharedMemorySize, GSMB);
    cudaFuncSetAttribute((const void*)mma_gemm<2>, cudaFuncAttributeMaxDynamicSharedMemorySize, GSMB);
    cudaFuncSetAttribute((const void*)attn_mma,    cudaFuncAttributeMaxDynamicSharedMemorySize, ATTN_SMEM);

    // 0. ONE fused pre-round launch: x + all 5 weights -> tf32 (RNA)
    round_all_kernel<<<592, 256>>>(
        x,    gxr,   NTOK*INDIM/4,
        Wf,   gwf,   DM*INDIM/4,
        Wqkv, gwqkv, 3*DM*DM/4,
        Wo,   gwo,   DM*DM/4,
        W1,   gw1,   FFD*DM/4,
        W2,   gw2,   DM*FFD/4);

    // 1. row_all
    rowall_kernel<<<NTOK, 128>>>(amask, grow);
    // 2. fuse projection: g_x = x @ Wf^T + bf
    mma_gemm<0><<<dim3(DM/128, NTOK/128), 256, GSMB>>>(gxr, gwf, bf, nullptr, gx, NTOK, DM, INDIM);
    // 3. LN1
    ln_kernel<<<NTOK, 128>>>(gx, ln1g, ln1b, gxn);
    // 4. qkv
    mma_gemm<0><<<dim3((3*DM)/128, NTOK/128), 256, GSMB>>>(gxn, gwqkv, bqkv, nullptr, gqkv, NTOK, 3*DM, DM);
    // 5. attention (128q CTAs)
    attn_mma<<<dim3(LSEQ/128, NH, BB), 256, ATTN_SMEM>>>(gqkv, amask, adj, grow, lscale, gctx);
    // 6. out proj + residual
    mma_gemm<2><<<dim3(DM/128, NTOK/128), 256, GSMB>>>(gctx, gwo, bo, gx, gx, NTOK, DM, DM);
    // 7. LN2
    ln_kernel<<<NTOK, 128>>>(gx, ln2g, ln2b, gxn);
    // 8. FFN up + GELU
    mma_gemm<1><<<dim3(FFD/128, NTOK/128), 256, GSMB>>>(gxn, gw1, b1, nullptr, gh, NTOK, FFD, DM);
    // 9. FFN down + residual -> out
    mma_gemm<2><<<dim3(DM/128, NTOK/128), 256, GSMB>>>(gh, gw2, b2, gx, out, NTOK, DM, FFD);
}

// round 14
// speedup vs baseline: 1.2223x; 1.0158x over previous
#include <cuda_runtime.h>
#include <math.h>
#include <stdint.h>

#define BB     4
#define LSEQ   1024
#define INDIM  256
#define DM     512
#define NH     8
#define DHD    64
#define FFD    2048
#define NTOK   (BB*LSEQ)   // 4096

// ---------------- scratch (device globals: allocation-free) ----------------
__device__ float g_x   [NTOK*DM];
__device__ float g_xn  [NTOK*DM];
__device__ float g_qkv [NTOK*3*DM];
__device__ float g_ctx [NTOK*DM];
__device__ float g_h   [NTOK*FFD];
__device__ unsigned char g_rowall[NTOK];
// tf32-pre-rounded GEMM inputs
__device__ float g_xr  [NTOK*INDIM];
__device__ float g_wf  [DM*INDIM];
__device__ float g_wqkv[3*DM*DM];
__device__ float g_wo  [DM*DM];
__device__ float g_w1  [FFD*DM];
__device__ float g_w2  [DM*FFD];

__device__ __forceinline__ uint32_t tf32r(float x) {
    uint32_t r; asm("cvt.rna.tf32.f32 %0, %1;" : "=r"(r) : "f"(x)); return r;
}
__device__ __forceinline__ float tf32f(float x) { return __uint_as_float(tf32r(x)); }
__device__ __forceinline__ void mma_tf32(float* c, const uint32_t* a, const uint32_t* b) {
    asm volatile(
        "mma.sync.aligned.m16n8k8.row.col.f32.tf32.tf32.f32 "
        "{%0,%1,%2,%3}, {%4,%5,%6,%7}, {%8,%9}, {%0,%1,%2,%3};"
        : "+f"(c[0]), "+f"(c[1]), "+f"(c[2]), "+f"(c[3])
        : "r"(a[0]), "r"(a[1]), "r"(a[2]), "r"(a[3]), "r"(b[0]), "r"(b[1]));
}
__device__ __forceinline__ uint32_t smem_u32(const void* p) {
    uint32_t a;
    asm("{ .reg .u64 t; cvta.to.shared.u64 t, %1; cvt.u32.u64 %0, t; }" : "=r"(a) : "l"(p));
    return a;
}
__device__ __forceinline__ void cpa16(uint32_t d, const void* s) {
    asm volatile("cp.async.ca.shared.global [%0], [%1], 16;" :: "r"(d), "l"(s));
}
__device__ __forceinline__ void cpa_commit() { asm volatile("cp.async.commit_group;" ::: "memory"); }
template<int N> __device__ __forceinline__ void cpa_wait() {
    asm volatile("cp.async.wait_group %0;" :: "n"(N) : "memory");
}

// ---------------- fused tf32 pre-round: all 6 tensors in one launch ----------
__global__ __launch_bounds__(256) void round_all_kernel(
    const float* __restrict__ s0, float* __restrict__ d0, int n0,
    const float* __restrict__ s1, float* __restrict__ d1, int n1,
    const float* __restrict__ s2, float* __restrict__ d2, int n2,
    const float* __restrict__ s3, float* __restrict__ d3, int n3,
    const float* __restrict__ s4, float* __restrict__ d4, int n4,
    const float* __restrict__ s5, float* __restrict__ d5, int n5)
{
    const int stride = gridDim.x * 256;
    const int base = blockIdx.x * 256 + threadIdx.x;
    #define RSEG(S, D, N) \
        for (int i = base; i < (N); i += stride) { \
            float4 v = ((const float4*)(S))[i]; \
            v.x = tf32f(v.x); v.y = tf32f(v.y); v.z = tf32f(v.z); v.w = tf32f(v.w); \
            ((float4*)(D))[i] = v; \
        }
    RSEG(s0, d0, n0) RSEG(s1, d1, n1) RSEG(s2, d2, n2)
    RSEG(s3, d3, n3) RSEG(s4, d4, n4) RSEG(s5, d5, n5)
    #undef RSEG
}

// ================= tf32 mma.sync GEMM, cp.async 2-stage (R8 proven config) ====
// EPI: 0=bias, 1=bias+GELU(+round), 2=bias+residual, 3=bias(+round)
#define RP   44
#define STGU (2 * 128 * RP)
#define GSMB (2 * STGU * 4)

template<int EPI>
__global__ __launch_bounds__(256, 2) void mma_gemm(
    const float* __restrict__ A, const float* __restrict__ W,
    const float* __restrict__ bias, const float* __restrict__ res,
    float* __restrict__ C, int M, int N, int K)
{
    extern __shared__ uint32_t sm[];
    const uint32_t sbase = smem_u32(sm);
    const int tid = threadIdx.x;
    const int bm = blockIdx.y * 128, bn = blockIdx.x * 128;
    const int lane = tid & 31, warp = tid >> 5;
    const int wm = warp & 3, wn = warp >> 2;
    const int m_base = wm * 32, n_base = wn * 64;
    const int lg = lane >> 2, lt = lane & 3;

    float acc[2][8][4];
    #pragma unroll
    for (int mt = 0; mt < 2; mt++)
        #pragma unroll
        for (int nt = 0; nt < 8; nt++)
            #pragma unroll
            for (int q = 0; q < 4; q++) acc[mt][nt][q] = 0.f;

    const int row = tid >> 3, kc = tid & 7;
    const float* Agp = A + (size_t)(bm + row) * K + kc * 4;
    const float* Bgp = W + (size_t)(bn + row) * K + kc * 4;
    const uint32_t sA_off = (row * RP + kc * 4) * 4;
    const uint32_t rowstride = 32 * RP * 4;
    const size_t gstride = (size_t)32 * K;

    const int nc = K / 32;
    {
        uint32_t sA = sbase + sA_off;
        uint32_t sB = sA + 128 * RP * 4;
        #pragma unroll
        for (int i = 0; i < 4; i++) {
            cpa16(sA + i * rowstride, Agp + i * gstride);
            cpa16(sB + i * rowstride, Bgp + i * gstride);
        }
        cpa_commit();
    }

    for (int c = 0; c < nc; c++) {
        const int st = c & 1;
        if (c + 1 < nc) {
            uint32_t sA = sbase + ((c + 1) & 1) * (STGU * 4) + sA_off;
            uint32_t sB = sA + 128 * RP * 4;
            const float* Ag = Agp + (c + 1) * 32;
            const float* Bg = Bgp + (c + 1) * 32;
            #pragma unroll
            for (int i = 0; i < 4; i++) {
                cpa16(sA + i * rowstride, Ag + i * gstride);
                cpa16(sB + i * rowstride, Bg + i * gstride);
            }
            cpa_commit();
            cpa_wait<1>();
        } else {
            cpa_wait<0>();
        }
        __syncthreads();

        const uint32_t* As = sm + st * STGU;
        const uint32_t* Bs = As + 128 * RP;
        #pragma unroll
        for (int ks = 0; ks < 4; ks++) {
            const int k = ks * 8;
            uint32_t a[2][4], b[8][2];
            #pragma unroll
            for (int mt = 0; mt < 2; mt++) {
                const int mr = m_base + mt * 16 + lg;
                a[mt][0] = As[mr * RP + k + lt];
                a[mt][1] = As[(mr + 8) * RP + k + lt];
                a[mt][2] = As[mr * RP + k + lt + 4];
                a[mt][3] = As[(mr + 8) * RP + k + lt + 4];
            }
            #pragma unroll
            for (int nt = 0; nt < 8; nt++) {
                const int nr = n_base + nt * 8 + lg;
                b[nt][0] = Bs[nr * RP + k + lt];
                b[nt][1] = Bs[nr * RP + k + lt + 4];
            }
            #pragma unroll
            for (int mt = 0; mt < 2; mt++)
                #pragma unroll
                for (int nt = 0; nt < 8; nt++)
                    mma_tf32(acc[mt][nt], a[mt], b[nt]);
        }
        __syncthreads();
    }

    #pragma unroll
    for (int mt = 0; mt < 2; mt++) {
        #pragma unroll
        for (int nt = 0; nt < 8; nt++) {
            const int rw = bm + m_base + mt * 16 + lg;
            const int col = bn + n_base + nt * 8 + lt * 2;
            #pragma unroll
            for (int half = 0; half < 2; half++) {
                const int r = rw + half * 8;
                float v0 = acc[mt][nt][half*2+0] + bias[col];
                float v1 = acc[mt][nt][half*2+1] + bias[col+1];
                if (EPI == 1) {
                    v0 = 0.5f * v0 * (1.f + erff(v0 * 0.70710678118654752f));
                    v1 = 0.5f * v1 * (1.f + erff(v1 * 0.70710678118654752f));
                    v0 = tf32f(v0); v1 = tf32f(v1);
                }
                if (EPI == 3) { v0 = tf32f(v0); v1 = tf32f(v1); }
                if (EPI == 2) {
                    float2 rr = *(const float2*)(res + (size_t)r * N + col);
                    v0 += rr.x; v1 += rr.y;
                }
                *(float2*)(C + (size_t)r * N + col) = make_float2(v0, v1);
            }
        }
    }
}

// ---------------- layernorm (tf32-rounded output) ----------------
__global__ __launch_bounds__(128) void ln_kernel(
    const float* __restrict__ X, const float* __restrict__ g,
    const float* __restrict__ b, float* __restrict__ Y)
{
    const int row = blockIdx.x;
    const int tid = threadIdx.x;
    float4 v = *(const float4*)(X + (size_t)row*DM + tid*4);
    float s  = v.x + v.y + v.z + v.w;
    float s2 = v.x*v.x + v.y*v.y + v.z*v.z + v.w*v.w;
    #pragma unroll
    for (int off = 16; off >= 1; off >>= 1) {
        s  += __shfl_xor_sync(0xffffffffu, s,  off);
        s2 += __shfl_xor_sync(0xffffffffu, s2, off);
    }
    __shared__ float sh[8];
    if ((tid & 31) == 0) { sh[tid>>5] = s; sh[4 + (tid>>5)] = s2; }
    __syncthreads();
    s  = sh[0] + sh[1] + sh[2] + sh[3];
    s2 = sh[4] + sh[5] + sh[6] + sh[7];
    float mu  = s * (1.f/DM);
    float var = s2 * (1.f/DM) - mu*mu;
    float inv = rsqrtf(var + 1e-5f);
    float4 gg = *(const float4*)(g + tid*4);
    float4 bb = *(const float4*)(b + tid*4);
    float4 y;
    y.x = tf32f((v.x - mu)*inv*gg.x + bb.x);
    y.y = tf32f((v.y - mu)*inv*gg.y + bb.y);
    y.z = tf32f((v.z - mu)*inv*gg.z + bb.z);
    y.w = tf32f((v.w - mu)*inv*gg.w + bb.w);
    *(float4*)(Y + (size_t)row*DM + tid*4) = y;
}

// ---------------- row_all (mask int32 0/1) ----------------
__global__ __launch_bounds__(128) void rowall_kernel(
    const int* __restrict__ mask, unsigned char* __restrict__ out)
{
    const int row = blockIdx.x;
    const int tid = threadIdx.x;
    const int* m = mask + (size_t)row * LSEQ;
    int mn = 1;
    #pragma unroll
    for (int c = 0; c < LSEQ / 512; c++) {
        int4 v = *(const int4*)(m + c*512 + tid*4);
        mn = min(mn, min(min(v.x, v.y), min(v.z, v.w)));
    }
    #pragma unroll
    for (int off = 16; off >= 1; off >>= 1)
        mn = min(mn, __shfl_xor_sync(0xffffffffu, mn, off));
    __shared__ int sh[4];
    if ((tid & 31) == 0) sh[tid>>5] = mn;
    __syncthreads();
    if (tid == 0) {
        int r = min(min(sh[0], sh[1]), min(sh[2], sh[3]));
        out[row] = (r != 0) ? 1 : 0;
    }
}

// ---------------- flash attention: 128q CTA + cp.async K/V double buffer -----
// qkv is pre-rounded tf32 (EPI=3) -> no conversion in the hot loop.
// smem: QP[128][68] (Q then P), K[2][64][68], V[2][64][72] = 104KB -> 2 CTAs/SM.
#define APAD 68
#define VPAD 72
#define SM_QP 0
#define SM_K  (128*APAD)
#define SM_V  (128*APAD + 2*64*APAD)
#define KSTG  (64*APAD)
#define VSTG  (64*VPAD)
#define ATTN_SMEM ((128*APAD + 2*64*APAD + 2*64*VPAD) * 4)

__global__ __launch_bounds__(256) void attn_mma(
    const float* __restrict__ qkv,
    const int* __restrict__ mask,
    const float* __restrict__ adj,
    const unsigned char* __restrict__ rowall,
    const float* __restrict__ logscale,
    float* __restrict__ ctx)
{
    extern __shared__ uint32_t sm[];
    uint32_t* QPs = sm + SM_QP;
    const uint32_t sbase = smem_u32(sm);
    const uint32_t kbase = sbase + SM_K * 4;
    const uint32_t vbase = sbase + SM_V * 4;

    const int b = blockIdx.z, h = blockIdx.y;
    const int q0 = blockIdx.x * 128;
    const int tid = threadIdx.x;
    const int lane = tid & 31, warp = tid >> 5;
    const int lg = lane >> 2, lt = lane & 3;
    const int mb = warp * 16;
    const float escale = expf(logscale[0]);

    // ---- load Q tile raw (pre-rounded tf32 bits) ----
    {
        const int lrow = tid >> 1, lcb = (tid & 1) * 32;
        const float* qg = qkv + (size_t)(b*LSEQ + q0 + lrow)*(3*DM) + h*DHD + lcb;
        #pragma unroll
        for (int i = 0; i < 8; i++)
            *(uint4*)(QPs + lrow*APAD + lcb + i*4) = *(const uint4*)(qg + i*4);
    }
    __syncthreads();

    // ---- hoist Q fragments (Qs smem dead afterwards -> reused as P) ----
    uint32_t qa[8][4];
    #pragma unroll
    for (int ks = 0; ks < 8; ks++) {
        const int k8 = ks * 8;
        qa[ks][0] = QPs[(mb+lg  )*APAD + k8 + lt];
        qa[ks][1] = QPs[(mb+lg+8)*APAD + k8 + lt];
        qa[ks][2] = QPs[(mb+lg  )*APAD + k8 + lt + 4];
        qa[ks][3] = QPs[(mb+lg+8)*APAD + k8 + lt + 4];
    }
    __syncthreads();   // all warps done reading Q before P overwrites

    float o[8][4];
    #pragma unroll
    for (int nt = 0; nt < 8; nt++)
        #pragma unroll
        for (int q = 0; q < 4; q++) o[nt][q] = 0.f;
    float mi[2] = {-1e30f, -1e30f}, li[2] = {0.f, 0.f};

    const int qrow[2] = { q0 + mb + lg, q0 + mb + lg + 8 };
    const bool raq[2] = { rowall[b*LSEQ + qrow[0]] != 0, rowall[b*LSEQ + qrow[1]] != 0 };

    // K staged by threads 0-127, V by threads 128-255 (8 x cp.async.16 each)
    const int lhalf = tid >> 7;
    const int lt128 = tid & 127;
    const int lrow = lt128 >> 1, lcb = (lt128 & 1) * 32;
    const float* kvg_base = qkv + (size_t)(b*LSEQ + lrow)*(3*DM)
                          + (lhalf ? 2*DM : DM) + h*DHD + lcb;
    const uint32_t s_off = (lhalf ? (uint32_t)(lrow*VPAD + lcb)
                                  : (uint32_t)(lrow*APAD + lcb)) * 4;
    const size_t kv_step = (size_t)64 * (3*DM);   // +64 seq rows

    // prologue: tile 0 -> stage 0
    {
        uint32_t dst = (lhalf ? vbase : kbase) + s_off;
        const float* src = kvg_base;
        #pragma unroll
        for (int i = 0; i < 8; i++) cpa16(dst + i*16, src + i*4);
        cpa_commit();
    }

    const int NTILE = LSEQ / 64;
    for (int t = 0; t < NTILE; t++) {
        const int st = t & 1;
        if (t + 1 < NTILE) {
            uint32_t dst = (lhalf ? vbase + ((t+1)&1)*VSTG*4
                                  : kbase + ((t+1)&1)*KSTG*4) + s_off;
            const float* src = kvg_base + (size_t)(t+1) * kv_step;
            #pragma unroll
            for (int i = 0; i < 8; i++) cpa16(dst + i*16, src + i*4);
            cpa_commit();
            cpa_wait<1>();
        } else {
            cpa_wait<0>();
        }
        __syncthreads();

        const uint32_t* Ks = sm + SM_K + st * KSTG;
        const uint32_t* Vs = sm + SM_V + st * VSTG;
        const int k0 = t * 64;

        // ---- S = Q @ K^T ----
        float s[8][4];
        #pragma unroll
        for (int nt = 0; nt < 8; nt++)
            #pragma unroll
            for (int q = 0; q < 4; q++) s[nt][q] = 0.f;
        #pragma unroll
        for (int ks = 0; ks < 8; ks++) {
            const int k8 = ks * 8;
            #pragma unroll
            for (int nt = 0; nt < 8; nt++) {
                uint32_t bfr[2];
                bfr[0] = Ks[(nt*8+lg)*APAD + k8 + lt];
                bfr[1] = Ks[(nt*8+lg)*APAD + k8 + lt + 4];
                mma_tf32(s[nt], qa[ks], bfr);
            }
        }

        // ---- bias + online softmax ----
        #pragma unroll
        for (int r = 0; r < 2; r++) {
            const int q = qrow[r];
            const size_t roff = ((size_t)b*LSEQ + q)*LSEQ + k0;
            float rmax = -1e30f;
            #pragma unroll
            for (int nt = 0; nt < 8; nt++) {
                const int col = nt*8 + lt*2;
                const int2 mm = *(const int2*)(mask + roff + col);
                const float2 ad = *(const float2*)(adj + roff + col);
                float a0 = fminf(fmaxf(ad.x, 0.f), 1.f);
                float a1 = fminf(fmaxf(ad.y, 0.f), 1.f);
                bool e0 = (mm.x != 0) && !((k0+col   == q) && raq[r]);
                bool e1 = (mm.y != 0) && !((k0+col+1 == q) && raq[r]);
                float v0 = s[nt][2*r  ]*0.125f + (e0 ? -10000.f : 0.f) + escale*a0;
                float v1 = s[nt][2*r+1]*0.125f + (e1 ? -10000.f : 0.f) + escale*a1;
                s[nt][2*r  ] = v0; s[nt][2*r+1] = v1;
                rmax = fmaxf(rmax, fmaxf(v0, v1));
            }
            rmax = fmaxf(rmax, __shfl_xor_sync(0xffffffffu, rmax, 1));
            rmax = fmaxf(rmax, __shfl_xor_sync(0xffffffffu, rmax, 2));
            float mnew = fmaxf(mi[r], rmax);
            float corr = __expf(mi[r] - mnew);
            float psum = 0.f;
            #pragma unroll
            for (int nt = 0; nt < 8; nt++) {
                float p0 = __expf(s[nt][2*r  ] - mnew);
                float p1 = __expf(s[nt][2*r+1] - mnew);
                s[nt][2*r] = p0; s[nt][2*r+1] = p1;
                psum += p0 + p1;
            }
            psum += __shfl_xor_sync(0xffffffffu, psum, 1);
            psum += __shfl_xor_sync(0xffffffffu, psum, 2);
            li[r] = li[r]*corr + psum;
            mi[r] = mnew;
            #pragma unroll
            for (int nt = 0; nt < 8; nt++) { o[nt][2*r] *= corr; o[nt][2*r+1] *= corr; }
            #pragma unroll
            for (int nt = 0; nt < 8; nt++) {
                uint32_t* pd = QPs + (mb+lg+8*r)*APAD + nt*8 + lt*2;
                pd[0] = tf32r(s[nt][2*r]); pd[1] = tf32r(s[nt][2*r+1]);
            }
        }
        __syncwarp();   // P rows are warp-local

        // ---- O += P @ V ----
        #pragma unroll
        for (int ks = 0; ks < 8; ks++) {
            const int k8 = ks * 8;
            uint32_t pa[4];
            pa[0] = QPs[(mb+lg  )*APAD + k8 + lt];
            pa[1] = QPs[(mb+lg+8)*APAD + k8 + lt];
            pa[2] = QPs[(mb+lg  )*APAD + k8 + lt + 4];
            pa[3] = QPs[(mb+lg+8)*APAD + k8 + lt + 4];
            #pragma unroll
            for (int nt = 0; nt < 8; nt++) {
                uint32_t bfr[2];
                bfr[0] = Vs[(k8+lt  )*VPAD + nt*8 + lg];
                bfr[1] = Vs[(k8+lt+4)*VPAD + nt*8 + lg];
                mma_tf32(o[nt], pa, bfr);
            }
        }
        __syncthreads();   // all reads of stage st done before t+2 overwrites it
    }

    const float inv0 = 1.f / li[0], inv1 = 1.f / li[1];
    #pragma unroll
    for (int nt = 0; nt < 8; nt++) {
        const int col = h*DHD + nt*8 + lt*2;
        *(float2*)(ctx + (size_t)(b*LSEQ + qrow[0])*DM + col) =
            make_float2(tf32f(o[nt][0]*inv0), tf32f(o[nt][1]*inv0));
        *(float2*)(ctx + (size_t)(b*LSEQ + qrow[1])*DM + col) =
            make_float2(tf32f(o[nt][2]*inv1), tf32f(o[nt][3]*inv1));
    }
}

// ---------------- launch ----------------
extern "C" void kernel_launch(void* const* d_in, const int* in_sizes, int n_in,
                              void* d_out, int out_size)
{
    (void)in_sizes; (void)n_in; (void)out_size;
    const float* x      = (const float*)d_in[0];
    const int*   amask  = (const int*)d_in[1];
    const float* adj    = (const float*)d_in[2];
    const float* Wf     = (const float*)d_in[3];
    const float* bf     = (const float*)d_in[4];
    const float* Wqkv   = (const float*)d_in[5];
    const float* bqkv   = (const float*)d_in[6];
    const float* Wo     = (const float*)d_in[7];
    const float* bo     = (const float*)d_in[8];
    const float* ln1g   = (const float*)d_in[9];
    const float* ln1b   = (const float*)d_in[10];
    const float* ln2g   = (const float*)d_in[11];
    const float* ln2b   = (const float*)d_in[12];
    const float* W1     = (const float*)d_in[13];
    const float* b1     = (const float*)d_in[14];
    const float* W2     = (const float*)d_in[15];
    const float* b2     = (const float*)d_in[16];
    const float* lscale = (const float*)d_in[17];
    float* out = (float*)d_out;

    float *gx, *gxn, *gqkv, *gctx, *gh;
    float *gxr, *gwf, *gwqkv, *gwo, *gw1, *gw2;
    unsigned char* grow;
    cudaGetSymbolAddress((void**)&gx,    g_x);
    cudaGetSymbolAddress((void**)&gxn,   g_xn);
    cudaGetSymbolAddress((void**)&gqkv,  g_qkv);
    cudaGetSymbolAddress((void**)&gctx,  g_ctx);
    cudaGetSymbolAddress((void**)&gh,    g_h);
    cudaGetSymbolAddress((void**)&grow,  g_rowall);
    cudaGetSymbolAddress((void**)&gxr,   g_xr);
    cudaGetSymbolAddress((void**)&gwf,   g_wf);
    cudaGetSymbolAddress((void**)&gwqkv, g_wqkv);
    cudaGetSymbolAddress((void**)&gwo,   g_wo);
    cudaGetSymbolAddress((void**)&gw1,   g_w1);
    cudaGetSymbolAddress((void**)&gw2,   g_w2);

    cudaFuncSetAttribute((const void*)mma_gemm<0>, cudaFuncAttributeMaxDynamicSharedMemorySize, GSMB);
    cudaFuncSetAttribute((const void*)mma_gemm<1>, cudaFuncAttributeMaxDynamicSharedMemorySize, GSMB);
    cudaFuncSetAttribute((const void*)mma_gemm<2>, cudaFuncAttributeMaxDynamicSharedMemorySize, GSMB);
    cudaFuncSetAttribute((const void*)mma_gemm<3>, cudaFuncAttributeMaxDynamicSharedMemorySize, GSMB);
    cudaFuncSetAttribute((const void*)attn_mma,    cudaFuncAttributeMaxDynamicSharedMemorySize, ATTN_SMEM);

    // 0. ONE fused pre-round launch: x + all 5 weights -> tf32 (RNA)
    round_all_kernel<<<592, 256>>>(
        x,    gxr,   NTOK*INDIM/4,
        Wf,   gwf,   DM*INDIM/4,
        Wqkv, gwqkv, 3*DM*DM/4,
        Wo,   gwo,   DM*DM/4,
        W1,   gw1,   FFD*DM/4,
        W2,   gw2,   DM*FFD/4);

    // 1. row_all
    rowall_kernel<<<NTOK, 128>>>(amask, grow);
    // 2. fuse projection: g_x = x @ Wf^T + bf  (fp32 residual stream)
    mma_gemm<0><<<dim3(DM/128, NTOK/128), 256, GSMB>>>(gxr, gwf, bf, nullptr, gx, NTOK, DM, INDIM);
    // 3. LN1
    ln_kernel<<<NTOK, 128>>>(gx, ln1g, ln1b, gxn);
    // 4. qkv (EPI=3: output pre-rounded tf32 for attention's cp.async path)
    mma_gemm<3><<<dim3((3*DM)/128, NTOK/128), 256, GSMB>>>(gxn, gwqkv, bqkv, nullptr, gqkv, NTOK, 3*DM, DM);
    // 5. attention (128q CTAs, cp.async K/V double buffer)
    attn_mma<<<dim3(LSEQ/128, NH, BB), 256, ATTN_SMEM>>>(gqkv, amask, adj, grow, lscale, gctx);
    // 6. out proj + residual
    mma_gemm<2><<<dim3(DM/128, NTOK/128), 256, GSMB>>>(gctx, gwo, bo, gx, gx, NTOK, DM, DM);
    // 7. LN2
    ln_kernel<<<NTOK, 128>>>(gx, ln2g, ln2b, gxn);
    // 8. FFN up + GELU
    mma_gemm<1><<<dim3(FFD/128, NTOK/128), 256, GSMB>>>(gxn, gw1, b1, nullptr, gh, NTOK, FFD, DM);
    // 9. FFN down + residual -> out
    mma_gemm<2><<<dim3(DM/128, NTOK/128), 256, GSMB>>>(gh, gw2, b2, gx, out, NTOK, DM, FFD);
}